// round 8
// baseline (speedup 1.0000x reference)
#include <cuda_runtime.h>
#include <cstdint>

// BatchedGAT round 7:
//   gemm_fused: h = x@W (fp32 f32x2) + fused e_src/e_dst (pre-scaled by log2e)
//               + tf32 B-fragment emission. (unchanged mainloop)
//   mask_kernel: adj > 0.5 -> 2MB packed bitmask (ballot order matched to
//               the attn inner loop's bit positions).
//   attn: flash-GAT via mma.sync tf32; adj replaced by register-resident
//         mask words; A-fragment tf32 rounding via IADD+AND (den consistent);
//         cp.async double-buffered fragments/es; launch_bounds(256,3).

#define DEV __device__ __forceinline__
using u64 = unsigned long long;
using u32 = unsigned int;

DEV u64 packff(float lo, float hi) {
    u64 r; asm("mov.b64 %0, {%1,%2};" : "=l"(r) : "f"(lo), "f"(hi)); return r;
}
DEV u64 fma2(u64 a, u64 b, u64 c) {
    u64 r; asm("fma.rn.f32x2 %0, %1, %2, %3;" : "=l"(r) : "l"(a), "l"(b), "l"(c)); return r;
}
DEV float2 unpackff(u64 v) {
    float lo, hi; asm("mov.b64 {%0,%1}, %2;" : "=f"(lo), "=f"(hi) : "l"(v));
    return make_float2(lo, hi);
}
DEV u32 cvt_tf32(float x) {
    u32 r; asm("cvt.rna.tf32.f32 %0, %1;" : "=r"(r) : "f"(x)); return r;
}
DEV float ex2f(float x) {
    float r; asm("ex2.approx.f32 %0, %1;" : "=f"(r) : "f"(x)); return r;
}
DEV u32 smem_u32(const void* p) {
    u32 a; asm("{ .reg .u64 t; cvta.to.shared.u64 t, %1; cvt.u32.u64 %0, t; }"
               : "=r"(a) : "l"(p));
    return a;
}
DEV void cpasync16(u32 dst, const void* src) {
    asm volatile("cp.async.cg.shared.global [%0], [%1], 16;"
                 :: "r"(dst), "l"(src) : "memory");
}
#define CP_COMMIT() asm volatile("cp.async.commit_group;" ::: "memory")
#define CP_WAIT1()  asm volatile("cp.async.wait_group 1;" ::: "memory")
#define CP_WAIT0()  asm volatile("cp.async.wait_group 0;" ::: "memory")

DEV void mma16n8k8(float* c, u32 a0, u32 a1, u32 a2, u32 a3, u32 b0, u32 b1) {
    asm volatile(
        "mma.sync.aligned.m16n8k8.row.col.f32.tf32.tf32.f32 "
        "{%0,%1,%2,%3}, {%4,%5,%6,%7}, {%8,%9}, {%0,%1,%2,%3};"
        : "+f"(c[0]), "+f"(c[1]), "+f"(c[2]), "+f"(c[3])
        : "r"(a0), "r"(a1), "r"(a2), "r"(a3), "r"(b0), "r"(b1));
}
// tf32 round-to-nearest on fp32 bits (half-up); maps p=0 -> 0.
DEV u32 rnd_tf32(float x) { return (__float_as_uint(x) + 0x1000u) & 0xFFFFE000u; }

constexpr int Bb = 16, Nn = 1024, Dd = 256, Hh = 4, HF = 256;
constexpr int Mrows = Bb * Nn;
constexpr float LOG2E = 1.4426950408889634f;

// e arrays transposed [h][b*N+n], PRE-SCALED by log2e.
__device__ float g_es[Hh * Mrows];
__device__ float g_ed[Hh * Mrows];
// B fragments: [bh][jb(128)][q(4)][lane(32)] uint4
__device__ uint4 g_hTf4[64 * 128 * 4 * 32];   // 16.8 MB
// adj bitmask: [row(16384)][kblk(8)][c(4)] u32; bit l of word (kblk,c)
// <-> j = 128*kblk + 4*l + c
__device__ u32 g_bm[Mrows * 32];              // 2 MB

// ---------------------------------------------------------------------------
// Kernel 1: gemm + fused e + fragment emission (mainloop unchanged).
// ---------------------------------------------------------------------------
__global__ __launch_bounds__(256) void gemm_fused(const float* __restrict__ A,
                                                  const float* __restrict__ W,
                                                  const float* __restrict__ a_src,
                                                  const float* __restrict__ a_dst) {
    __shared__ float As[16][128];
    __shared__ float Bs[16][64];
    __shared__ float hs[128][68];

    const int tid = threadIdx.x;
    const int bm = blockIdx.y, bn = blockIdx.x;
    const int ty = tid >> 4, tx = tid & 15;

    u64 acc[16];
#pragma unroll
    for (int i = 0; i < 16; ++i) acc[i] = 0ull;

    const float* Ab = A + bm * 128 * Dd;
    const float* Wb = W + bn * 64;
    const int arow = tid >> 2, acol = (tid & 3) << 2;
    const int brow = tid >> 4, bcol = (tid & 15) << 2;

    for (int kt = 0; kt < Dd; kt += 16) {
        float4 a0 = *(const float4*)(Ab + arow * Dd + kt + acol);
        float4 a1 = *(const float4*)(Ab + (arow + 64) * Dd + kt + acol);
        float4 bv = *(const float4*)(Wb + (kt + brow) * HF + bcol);
        __syncthreads();
        As[acol + 0][arow] = a0.x; As[acol + 1][arow] = a0.y;
        As[acol + 2][arow] = a0.z; As[acol + 3][arow] = a0.w;
        As[acol + 0][arow + 64] = a1.x; As[acol + 1][arow + 64] = a1.y;
        As[acol + 2][arow + 64] = a1.z; As[acol + 3][arow + 64] = a1.w;
        *(float4*)&Bs[brow][bcol] = bv;
        __syncthreads();
#pragma unroll
        for (int kk = 0; kk < 16; ++kk) {
            ulonglong2 a01 = *(const ulonglong2*)&As[kk][ty * 4];
            ulonglong2 a23 = *(const ulonglong2*)&As[kk][64 + ty * 4];
            float4 b = *(const float4*)&Bs[kk][tx * 4];
            u64 av[4] = { a01.x, a01.y, a23.x, a23.y };
            u64 bp[4] = { packff(b.x, b.x), packff(b.y, b.y),
                          packff(b.z, b.z), packff(b.w, b.w) };
#pragma unroll
            for (int m2 = 0; m2 < 4; ++m2)
#pragma unroll
                for (int n = 0; n < 4; ++n)
                    acc[m2 * 4 + n] = fma2(av[m2], bp[n], acc[m2 * 4 + n]);
        }
    }

    // ---- epilogue ----
    const float4 as4 = *(const float4*)&a_src[bn * 64 + tx * 4];
    const float4 ad4 = *(const float4*)&a_dst[bn * 64 + tx * 4];
    float ps[8], pd[8];
#pragma unroll
    for (int r = 0; r < 8; ++r) { ps[r] = 0.f; pd[r] = 0.f; }

#pragma unroll
    for (int m2 = 0; m2 < 4; ++m2) {
        const int rloc = ((m2 >= 2) ? 64 : 0) + ty * 4 + (m2 & 1) * 2;
        float2 p0 = unpackff(acc[m2 * 4 + 0]);
        float2 p1 = unpackff(acc[m2 * 4 + 1]);
        float2 p2 = unpackff(acc[m2 * 4 + 2]);
        float2 p3 = unpackff(acc[m2 * 4 + 3]);
        hs[rloc][tx * 4 + 0] = p0.x;  hs[rloc + 1][tx * 4 + 0] = p0.y;
        hs[rloc][tx * 4 + 1] = p1.x;  hs[rloc + 1][tx * 4 + 1] = p1.y;
        hs[rloc][tx * 4 + 2] = p2.x;  hs[rloc + 1][tx * 4 + 2] = p2.y;
        hs[rloc][tx * 4 + 3] = p3.x;  hs[rloc + 1][tx * 4 + 3] = p3.y;
        ps[m2 * 2] = fmaf(p0.x, as4.x, fmaf(p1.x, as4.y,
                     fmaf(p2.x, as4.z, fmaf(p3.x, as4.w, ps[m2 * 2]))));
        ps[m2 * 2 + 1] = fmaf(p0.y, as4.x, fmaf(p1.y, as4.y,
                     fmaf(p2.y, as4.z, fmaf(p3.y, as4.w, ps[m2 * 2 + 1]))));
        pd[m2 * 2] = fmaf(p0.x, ad4.x, fmaf(p1.x, ad4.y,
                     fmaf(p2.x, ad4.z, fmaf(p3.x, ad4.w, pd[m2 * 2]))));
        pd[m2 * 2 + 1] = fmaf(p0.y, ad4.x, fmaf(p1.y, ad4.y,
                     fmaf(p2.y, ad4.z, fmaf(p3.y, ad4.w, pd[m2 * 2 + 1]))));
    }

#pragma unroll
    for (int r = 0; r < 8; ++r) {
#pragma unroll
        for (int o = 1; o < 16; o <<= 1) {
            ps[r] += __shfl_xor_sync(0xffffffffu, ps[r], o);
            pd[r] += __shfl_xor_sync(0xffffffffu, pd[r], o);
        }
    }
    if ((tid & 15) == 0) {
#pragma unroll
        for (int m2 = 0; m2 < 4; ++m2) {
            const int rloc = ((m2 >= 2) ? 64 : 0) + ty * 4 + (m2 & 1) * 2;
            const int rg = bm * 128 + rloc;
            g_es[bn * Mrows + rg]     = ps[m2 * 2] * LOG2E;
            g_es[bn * Mrows + rg + 1] = ps[m2 * 2 + 1] * LOG2E;
            g_ed[bn * Mrows + rg]     = pd[m2 * 2] * LOG2E;
            g_ed[bn * Mrows + rg + 1] = pd[m2 * 2 + 1] * LOG2E;
        }
    }
    __syncthreads();

    const int b_ = bm >> 3;
    const int bh = b_ * 4 + bn;
    const int jb0 = (bm & 7) * 16;
#pragma unroll
    for (int q2 = 0; q2 < 8; ++q2) {
        int v = (q2 << 8) + tid;
        int jbl = v >> 7;
        int q = (v >> 5) & 3;
        int ln = v & 31;
        int jl = jbl * 8 + (ln & 3);
        int f0 = (2 * q) * 8 + (ln >> 2);
        uint4 o;
        o.x = cvt_tf32(hs[jl][f0]);
        o.y = cvt_tf32(hs[jl + 4][f0]);
        o.z = cvt_tf32(hs[jl][f0 + 8]);
        o.w = cvt_tf32(hs[jl + 4][f0 + 8]);
        g_hTf4[(size_t)((bh * 128 + jb0 + jbl) * 4 + q) * 32 + ln] = o;
    }
}

// ---------------------------------------------------------------------------
// Kernel 2: adj -> packed bitmask. Warp covers one row; lane reads float4 at
// j = 128k + 4*lane; ballot per component c -> word (k, c).
// ---------------------------------------------------------------------------
__global__ __launch_bounds__(256) void mask_kernel(const float* __restrict__ adj) {
    const int wid = threadIdx.x >> 5, lane = threadIdx.x & 31;
    const int row = blockIdx.x * 8 + wid;
    const float4* src = (const float4*)(adj + (size_t)row * Nn);
#pragma unroll
    for (int k = 0; k < 8; ++k) {
        float4 v = __ldg(src + (k << 5) + lane);
        u32 b0 = __ballot_sync(0xffffffffu, v.x > 0.5f);
        u32 b1 = __ballot_sync(0xffffffffu, v.y > 0.5f);
        u32 b2 = __ballot_sync(0xffffffffu, v.w > 0.5f);   // placeholder order fix below
        u32 b2r = __ballot_sync(0xffffffffu, v.z > 0.5f);
        if (lane < 4) {
            u32 w = (lane == 0) ? b0 : (lane == 1) ? b1 : (lane == 2) ? b2r : b2;
            g_bm[row * 32 + (k << 2) + lane] = w;
        }
    }
}

// ---------------------------------------------------------------------------
// Kernel 3: flash-GAT attention. Grid (8 i-tiles, 64 bh), 256 thr.
// smem 34.3KB; masks live in registers.
// ---------------------------------------------------------------------------
constexpr int OFF_HF0 = 0;
constexpr int OFF_HF1 = 16384;
constexpr int OFF_ES0 = 32768;
constexpr int OFF_ES1 = 33024;
constexpr int OFF_ED  = 33280;
constexpr int OFF_DEN = 33792;
constexpr int SMEM_ATTN = 34304;

__global__ __launch_bounds__(256, 3) void attn_kernel(const float* __restrict__ bias,
                                                      float* __restrict__ out) {
    extern __shared__ char dsm[];
    const u32 sbase = smem_u32(dsm);
    float* ed_sm  = (float*)(dsm + OFF_ED);
    float* den_sm = (float*)(dsm + OFF_DEN);

    const int tid = threadIdx.x;
    const int w = tid >> 5, lane = tid & 31;
    const int bh = blockIdx.y, b = bh >> 2, h = bh & 3;
    const int i0 = blockIdx.x << 7;
    const int i_w = w << 4;
    const int grp = lane >> 2;
    const int tig = lane & 3;

    const u32 hf_off[2] = { sbase + OFF_HF0, sbase + OFF_HF1 };
    const u32 es_off[2] = { sbase + OFF_ES0, sbase + OFF_ES1 };

    const uint4* hf_base = g_hTf4 + (size_t)bh * 128 * 4 * 32;
    const float* es_base = g_es + h * Mrows + b * Nn;
    const u32* bmp0 = g_bm + (size_t)(b * Nn + i0 + i_w + grp) * 32 + tig;
    const u32* bmp1 = bmp0 + 8 * 32;

    auto stage = [&](int jt, int sel) {
        const uint4* hsrc = hf_base + (size_t)(jt * 8) * 4 * 32;
#pragma unroll
        for (int q = 0; q < 4; ++q)
            cpasync16(hf_off[sel] + (u32)((q << 8) + tid) * 16u, hsrc + (q << 8) + tid);
        if (tid < 16)
            cpasync16(es_off[sel] + (u32)tid * 16u, es_base + (jt << 6) + tid * 4);
    };

    stage(0, 0); CP_COMMIT();
    if (tid < 128) ed_sm[tid] = g_ed[h * Mrows + b * Nn + i0 + tid];

    float acc[8][4];
#pragma unroll
    for (int n = 0; n < 8; ++n)
#pragma unroll
        for (int k = 0; k < 4; ++k) acc[n][k] = 0.f;
    float den0 = 0.f, den1 = 0.f;

    u32 mA = __ldg(bmp0), mB = __ldg(bmp1);   // kblk 0

    __syncthreads();
    const float ed0 = ed_sm[i_w + grp];
    const float ed1 = ed_sm[i_w + 8 + grp];

    for (int jt = 0; jt < 16; ++jt) {
        const int sel = jt & 1;
        if (jt < 15) { stage(jt + 1, sel ^ 1); CP_COMMIT(); }
        u32 nA = mA, nB = mB;
        if (jt < 15) {
            const int kb = ((jt + 1) >> 1) << 2;
            nA = __ldg(bmp0 + kb);
            nB = __ldg(bmp1 + kb);
        }
        if (jt < 15) CP_WAIT1(); else CP_WAIT0();
        __syncthreads();

        const uint4* hfrag = (const uint4*)(dsm + (sel ? OFF_HF1 : OFF_HF0));
        const float* es_sm = (const float*)(dsm + (sel ? OFF_ES1 : OFF_ES0));

        const u32 mAh = mA >> ((jt & 1) << 4);
        const u32 mBh = mB >> ((jt & 1) << 4);

#pragma unroll
        for (int ks = 0; ks < 8; ++ks) {
            const int jj = (ks << 3) + tig;
            const float es0 = es_sm[jj];
            const float es1 = es_sm[jj + 4];
            const u32 s0 = mAh >> (2 * ks);
            const u32 s1 = mBh >> (2 * ks);

            float l00 = ed0 + es0; l00 = fmaxf(l00, 0.2f * l00);
            float l10 = ed1 + es0; l10 = fmaxf(l10, 0.2f * l10);
            float l01 = ed0 + es1; l01 = fmaxf(l01, 0.2f * l01);
            float l11 = ed1 + es1; l11 = fmaxf(l11, 0.2f * l11);
            float p00 = (s0 & 1u) ? ex2f(l00) : 0.f;
            float p10 = (s1 & 1u) ? ex2f(l10) : 0.f;
            float p01 = (s0 & 2u) ? ex2f(l01) : 0.f;
            float p11 = (s1 & 2u) ? ex2f(l11) : 0.f;

            const u32 a0 = rnd_tf32(p00);
            const u32 a1 = rnd_tf32(p10);
            const u32 a2 = rnd_tf32(p01);
            const u32 a3 = rnd_tf32(p11);
            den0 += __uint_as_float(a0) + __uint_as_float(a2);
            den1 += __uint_as_float(a1) + __uint_as_float(a3);

            const uint4* hrow = hfrag + (ks << 7) + lane;
#pragma unroll
            for (int q = 0; q < 4; ++q) {
                uint4 bf = hrow[q << 5];
                mma16n8k8(acc[2 * q],     a0, a1, a2, a3, bf.x, bf.y);
                mma16n8k8(acc[2 * q + 1], a0, a1, a2, a3, bf.z, bf.w);
            }
        }
        __syncthreads();
        mA = nA; mB = nB;
    }

    den0 += __shfl_xor_sync(0xffffffffu, den0, 1);
    den0 += __shfl_xor_sync(0xffffffffu, den0, 2);
    den1 += __shfl_xor_sync(0xffffffffu, den1, 1);
    den1 += __shfl_xor_sync(0xffffffffu, den1, 2);
    if (tig == 0) {
        den_sm[i_w + grp] = den0;
        den_sm[i_w + 8 + grp] = den1;
    }
    __syncthreads();
    const float inv0 = 1.0f / den_sm[i_w + grp];
    const float inv1 = 1.0f / den_sm[i_w + 8 + grp];

    float* o0 = out + (size_t)(b * Nn + i0 + i_w + grp) * HF + h * 64;
    float* o1 = out + (size_t)(b * Nn + i0 + i_w + 8 + grp) * HF + h * 64;
#pragma unroll
    for (int n = 0; n < 8; ++n) {
        const int col = (n << 3) + (tig << 1);
        float2 bz = *(const float2*)&bias[h * 64 + col];
        float2 r0, r1;
        r0.x = acc[n][0] * inv0 + bz.x;  r0.y = acc[n][1] * inv0 + bz.y;
        r1.x = acc[n][2] * inv1 + bz.x;  r1.y = acc[n][3] * inv1 + bz.y;
        *(float2*)&o0[col] = r0;
        *(float2*)&o1[col] = r1;
    }
}

// ---------------------------------------------------------------------------
extern "C" void kernel_launch(void* const* d_in, const int* in_sizes, int n_in,
                              void* d_out, int out_size) {
    (void)in_sizes; (void)n_in; (void)out_size;
    const float* x     = (const float*)d_in[0];
    const float* adj   = (const float*)d_in[1];
    const float* W     = (const float*)d_in[2];
    const float* a_src = (const float*)d_in[3];
    const float* a_dst = (const float*)d_in[4];
    const float* bias  = (const float*)d_in[5];
    float* out = (float*)d_out;

    cudaFuncSetAttribute(attn_kernel,
                         cudaFuncAttributeMaxDynamicSharedMemorySize, SMEM_ATTN);

    mask_kernel<<<Mrows / 8, 256>>>(adj);
    gemm_fused<<<dim3(HF / 64, Mrows / 128), 256>>>(x, W, a_src, a_dst);
    attn_kernel<<<dim3(8, 64), 256, SMEM_ATTN>>>(bias, out);
}

// round 9
// speedup vs baseline: 1.5371x; 1.5371x over previous
#include <cuda_runtime.h>
#include <cstdint>

// BatchedGAT round 8:
//   gemm_fused: h = x@W (fp32 f32x2) + fused e (log2e-scaled) + tf32
//               B-fragment emission; epilogue smem UNIONED with mainloop
//               tiles (occupancy 2 -> 3 CTAs/SM).
//   mask_kernel: adj > 0.5 -> 2MB bitmask, loads front-batched (MLP=8).
//   attn: flash-GAT mma.sync tf32, register-resident masks, cp.async
//         double-buffered fragments/es. launch_bounds(256,2) — R7's (256,3)
//         caused register spills and a 2x regression.

#define DEV __device__ __forceinline__
using u64 = unsigned long long;
using u32 = unsigned int;

DEV u64 packff(float lo, float hi) {
    u64 r; asm("mov.b64 %0, {%1,%2};" : "=l"(r) : "f"(lo), "f"(hi)); return r;
}
DEV u64 fma2(u64 a, u64 b, u64 c) {
    u64 r; asm("fma.rn.f32x2 %0, %1, %2, %3;" : "=l"(r) : "l"(a), "l"(b), "l"(c)); return r;
}
DEV float2 unpackff(u64 v) {
    float lo, hi; asm("mov.b64 {%0,%1}, %2;" : "=f"(lo), "=f"(hi) : "l"(v));
    return make_float2(lo, hi);
}
DEV u32 cvt_tf32(float x) {
    u32 r; asm("cvt.rna.tf32.f32 %0, %1;" : "=r"(r) : "f"(x)); return r;
}
DEV float ex2f(float x) {
    float r; asm("ex2.approx.f32 %0, %1;" : "=f"(r) : "f"(x)); return r;
}
DEV u32 smem_u32(const void* p) {
    u32 a; asm("{ .reg .u64 t; cvta.to.shared.u64 t, %1; cvt.u32.u64 %0, t; }"
               : "=r"(a) : "l"(p));
    return a;
}
DEV void cpasync16(u32 dst, const void* src) {
    asm volatile("cp.async.cg.shared.global [%0], [%1], 16;"
                 :: "r"(dst), "l"(src) : "memory");
}
#define CP_COMMIT() asm volatile("cp.async.commit_group;" ::: "memory")
#define CP_WAIT1()  asm volatile("cp.async.wait_group 1;" ::: "memory")
#define CP_WAIT0()  asm volatile("cp.async.wait_group 0;" ::: "memory")

DEV void mma16n8k8(float* c, u32 a0, u32 a1, u32 a2, u32 a3, u32 b0, u32 b1) {
    asm volatile(
        "mma.sync.aligned.m16n8k8.row.col.f32.tf32.tf32.f32 "
        "{%0,%1,%2,%3}, {%4,%5,%6,%7}, {%8,%9}, {%0,%1,%2,%3};"
        : "+f"(c[0]), "+f"(c[1]), "+f"(c[2]), "+f"(c[3])
        : "r"(a0), "r"(a1), "r"(a2), "r"(a3), "r"(b0), "r"(b1));
}
// tf32 round-to-nearest (half-up) on fp32 bits; maps p=0 -> 0.
DEV u32 rnd_tf32(float x) { return (__float_as_uint(x) + 0x1000u) & 0xFFFFE000u; }

constexpr int Bb = 16, Nn = 1024, Dd = 256, Hh = 4, HF = 256;
constexpr int Mrows = Bb * Nn;
constexpr float LOG2E = 1.4426950408889634f;

// e arrays transposed [h][b*N+n], PRE-SCALED by log2e.
__device__ float g_es[Hh * Mrows];
__device__ float g_ed[Hh * Mrows];
// B fragments: [bh][jb(128)][q(4)][lane(32)] uint4
__device__ uint4 g_hTf4[64 * 128 * 4 * 32];   // 16.8 MB
// adj bitmask: [row(16384)][kblk(8)][c(4)] u32; bit l of word (kblk,c)
// <-> j = 128*kblk + 4*l + c
__device__ u32 g_bm[Mrows * 32];              // 2 MB

// ---------------------------------------------------------------------------
// Kernel 1: gemm + fused e + fragment emission.
// Epilogue bounce hs UNIONED with mainloop As/Bs (temporally disjoint).
// ---------------------------------------------------------------------------
__global__ __launch_bounds__(256) void gemm_fused(const float* __restrict__ A,
                                                  const float* __restrict__ W,
                                                  const float* __restrict__ a_src,
                                                  const float* __restrict__ a_dst) {
    __shared__ union SmemU {
        struct { float As[16][128]; float Bs[16][64]; } ml;
        float hs[128][68];
    } su;

    const int tid = threadIdx.x;
    const int bm = blockIdx.y, bn = blockIdx.x;
    const int ty = tid >> 4, tx = tid & 15;

    u64 acc[16];
#pragma unroll
    for (int i = 0; i < 16; ++i) acc[i] = 0ull;

    const float* Ab = A + bm * 128 * Dd;
    const float* Wb = W + bn * 64;
    const int arow = tid >> 2, acol = (tid & 3) << 2;
    const int brow = tid >> 4, bcol = (tid & 15) << 2;

    for (int kt = 0; kt < Dd; kt += 16) {
        float4 a0 = *(const float4*)(Ab + arow * Dd + kt + acol);
        float4 a1 = *(const float4*)(Ab + (arow + 64) * Dd + kt + acol);
        float4 bv = *(const float4*)(Wb + (kt + brow) * HF + bcol);
        __syncthreads();
        su.ml.As[acol + 0][arow] = a0.x; su.ml.As[acol + 1][arow] = a0.y;
        su.ml.As[acol + 2][arow] = a0.z; su.ml.As[acol + 3][arow] = a0.w;
        su.ml.As[acol + 0][arow + 64] = a1.x; su.ml.As[acol + 1][arow + 64] = a1.y;
        su.ml.As[acol + 2][arow + 64] = a1.z; su.ml.As[acol + 3][arow + 64] = a1.w;
        *(float4*)&su.ml.Bs[brow][bcol] = bv;
        __syncthreads();
#pragma unroll
        for (int kk = 0; kk < 16; ++kk) {
            ulonglong2 a01 = *(const ulonglong2*)&su.ml.As[kk][ty * 4];
            ulonglong2 a23 = *(const ulonglong2*)&su.ml.As[kk][64 + ty * 4];
            float4 b = *(const float4*)&su.ml.Bs[kk][tx * 4];
            u64 av[4] = { a01.x, a01.y, a23.x, a23.y };
            u64 bp[4] = { packff(b.x, b.x), packff(b.y, b.y),
                          packff(b.z, b.z), packff(b.w, b.w) };
#pragma unroll
            for (int m2 = 0; m2 < 4; ++m2)
#pragma unroll
                for (int n = 0; n < 4; ++n)
                    acc[m2 * 4 + n] = fma2(av[m2], bp[n], acc[m2 * 4 + n]);
        }
    }
    __syncthreads();   // all warps done reading As/Bs before hs overwrites

    // ---- epilogue: hs store + e partials ----
    const float4 as4 = *(const float4*)&a_src[bn * 64 + tx * 4];
    const float4 ad4 = *(const float4*)&a_dst[bn * 64 + tx * 4];
    float ps[8], pd[8];
#pragma unroll
    for (int r = 0; r < 8; ++r) { ps[r] = 0.f; pd[r] = 0.f; }

#pragma unroll
    for (int m2 = 0; m2 < 4; ++m2) {
        const int rloc = ((m2 >= 2) ? 64 : 0) + ty * 4 + (m2 & 1) * 2;
        float2 p0 = unpackff(acc[m2 * 4 + 0]);
        float2 p1 = unpackff(acc[m2 * 4 + 1]);
        float2 p2 = unpackff(acc[m2 * 4 + 2]);
        float2 p3 = unpackff(acc[m2 * 4 + 3]);
        su.hs[rloc][tx * 4 + 0] = p0.x;  su.hs[rloc + 1][tx * 4 + 0] = p0.y;
        su.hs[rloc][tx * 4 + 1] = p1.x;  su.hs[rloc + 1][tx * 4 + 1] = p1.y;
        su.hs[rloc][tx * 4 + 2] = p2.x;  su.hs[rloc + 1][tx * 4 + 2] = p2.y;
        su.hs[rloc][tx * 4 + 3] = p3.x;  su.hs[rloc + 1][tx * 4 + 3] = p3.y;
        ps[m2 * 2] = fmaf(p0.x, as4.x, fmaf(p1.x, as4.y,
                     fmaf(p2.x, as4.z, fmaf(p3.x, as4.w, ps[m2 * 2]))));
        ps[m2 * 2 + 1] = fmaf(p0.y, as4.x, fmaf(p1.y, as4.y,
                     fmaf(p2.y, as4.z, fmaf(p3.y, as4.w, ps[m2 * 2 + 1]))));
        pd[m2 * 2] = fmaf(p0.x, ad4.x, fmaf(p1.x, ad4.y,
                     fmaf(p2.x, ad4.z, fmaf(p3.x, ad4.w, pd[m2 * 2]))));
        pd[m2 * 2 + 1] = fmaf(p0.y, ad4.x, fmaf(p1.y, ad4.y,
                     fmaf(p2.y, ad4.z, fmaf(p3.y, ad4.w, pd[m2 * 2 + 1]))));
    }

#pragma unroll
    for (int r = 0; r < 8; ++r) {
#pragma unroll
        for (int o = 1; o < 16; o <<= 1) {
            ps[r] += __shfl_xor_sync(0xffffffffu, ps[r], o);
            pd[r] += __shfl_xor_sync(0xffffffffu, pd[r], o);
        }
    }
    if ((tid & 15) == 0) {
#pragma unroll
        for (int m2 = 0; m2 < 4; ++m2) {
            const int rloc = ((m2 >= 2) ? 64 : 0) + ty * 4 + (m2 & 1) * 2;
            const int rg = bm * 128 + rloc;
            g_es[bn * Mrows + rg]     = ps[m2 * 2] * LOG2E;
            g_es[bn * Mrows + rg + 1] = ps[m2 * 2 + 1] * LOG2E;
            g_ed[bn * Mrows + rg]     = pd[m2 * 2] * LOG2E;
            g_ed[bn * Mrows + rg + 1] = pd[m2 * 2 + 1] * LOG2E;
        }
    }
    __syncthreads();   // hs ready

    // ---- fragment emission ----
    const int b_ = bm >> 3;
    const int bh = b_ * 4 + bn;
    const int jb0 = (bm & 7) * 16;
#pragma unroll
    for (int q2 = 0; q2 < 8; ++q2) {
        int v = (q2 << 8) + tid;
        int jbl = v >> 7;
        int q = (v >> 5) & 3;
        int ln = v & 31;
        int jl = jbl * 8 + (ln & 3);
        int f0 = (2 * q) * 8 + (ln >> 2);
        uint4 o;
        o.x = cvt_tf32(su.hs[jl][f0]);
        o.y = cvt_tf32(su.hs[jl + 4][f0]);
        o.z = cvt_tf32(su.hs[jl][f0 + 8]);
        o.w = cvt_tf32(su.hs[jl + 4][f0 + 8]);
        g_hTf4[(size_t)((bh * 128 + jb0 + jbl) * 4 + q) * 32 + ln] = o;
    }
}

// ---------------------------------------------------------------------------
// Kernel 2: adj -> bitmask; loads front-batched for MLP=8.
// ---------------------------------------------------------------------------
__global__ __launch_bounds__(256) void mask_kernel(const float* __restrict__ adj) {
    const int wid = threadIdx.x >> 5, lane = threadIdx.x & 31;
    const int row = blockIdx.x * 8 + wid;
    const float4* src = (const float4*)(adj + (size_t)row * Nn);
    float4 v[8];
#pragma unroll
    for (int k = 0; k < 8; ++k) v[k] = __ldg(src + (k << 5) + lane);
#pragma unroll
    for (int k = 0; k < 8; ++k) {
        u32 b0 = __ballot_sync(0xffffffffu, v[k].x > 0.5f);
        u32 b1 = __ballot_sync(0xffffffffu, v[k].y > 0.5f);
        u32 b2 = __ballot_sync(0xffffffffu, v[k].z > 0.5f);
        u32 b3 = __ballot_sync(0xffffffffu, v[k].w > 0.5f);
        if (lane < 4) {
            u32 w = (lane == 0) ? b0 : (lane == 1) ? b1 : (lane == 2) ? b2 : b3;
            g_bm[row * 32 + (k << 2) + lane] = w;
        }
    }
}

// ---------------------------------------------------------------------------
// Kernel 3: flash-GAT attention. launch_bounds(256,2) — no reg cap, no spill.
// ---------------------------------------------------------------------------
constexpr int OFF_HF0 = 0;
constexpr int OFF_HF1 = 16384;
constexpr int OFF_ES0 = 32768;
constexpr int OFF_ES1 = 33024;
constexpr int OFF_ED  = 33280;
constexpr int OFF_DEN = 33792;
constexpr int SMEM_ATTN = 34304;

__global__ __launch_bounds__(256, 2) void attn_kernel(const float* __restrict__ bias,
                                                      float* __restrict__ out) {
    extern __shared__ char dsm[];
    const u32 sbase = smem_u32(dsm);
    float* ed_sm  = (float*)(dsm + OFF_ED);
    float* den_sm = (float*)(dsm + OFF_DEN);

    const int tid = threadIdx.x;
    const int w = tid >> 5, lane = tid & 31;
    const int bh = blockIdx.y, b = bh >> 2, h = bh & 3;
    const int i0 = blockIdx.x << 7;
    const int i_w = w << 4;
    const int grp = lane >> 2;
    const int tig = lane & 3;

    const u32 hf_off[2] = { sbase + OFF_HF0, sbase + OFF_HF1 };
    const u32 es_off[2] = { sbase + OFF_ES0, sbase + OFF_ES1 };

    const uint4* hf_base = g_hTf4 + (size_t)bh * 128 * 4 * 32;
    const float* es_base = g_es + h * Mrows + b * Nn;
    const u32* bmp0 = g_bm + (size_t)(b * Nn + i0 + i_w + grp) * 32 + tig;
    const u32* bmp1 = bmp0 + 8 * 32;

    auto stage = [&](int jt, int sel) {
        const uint4* hsrc = hf_base + (size_t)(jt * 8) * 4 * 32;
#pragma unroll
        for (int q = 0; q < 4; ++q)
            cpasync16(hf_off[sel] + (u32)((q << 8) + tid) * 16u, hsrc + (q << 8) + tid);
        if (tid < 16)
            cpasync16(es_off[sel] + (u32)tid * 16u, es_base + (jt << 6) + tid * 4);
    };

    stage(0, 0); CP_COMMIT();
    if (tid < 128) ed_sm[tid] = g_ed[h * Mrows + b * Nn + i0 + tid];

    float acc[8][4];
#pragma unroll
    for (int n = 0; n < 8; ++n)
#pragma unroll
        for (int k = 0; k < 4; ++k) acc[n][k] = 0.f;
    float den0 = 0.f, den1 = 0.f;

    u32 mA = __ldg(bmp0), mB = __ldg(bmp1);   // kblk 0

    __syncthreads();
    const float ed0 = ed_sm[i_w + grp];
    const float ed1 = ed_sm[i_w + 8 + grp];

    for (int jt = 0; jt < 16; ++jt) {
        const int sel = jt & 1;
        if (jt < 15) { stage(jt + 1, sel ^ 1); CP_COMMIT(); }
        u32 nA = mA, nB = mB;
        if (jt < 15) {
            const int kb = ((jt + 1) >> 1) << 2;
            nA = __ldg(bmp0 + kb);
            nB = __ldg(bmp1 + kb);
        }
        if (jt < 15) CP_WAIT1(); else CP_WAIT0();
        __syncthreads();

        const uint4* hfrag = (const uint4*)(dsm + (sel ? OFF_HF1 : OFF_HF0));
        const float* es_sm = (const float*)(dsm + (sel ? OFF_ES1 : OFF_ES0));

        const u32 mAh = mA >> ((jt & 1) << 4);
        const u32 mBh = mB >> ((jt & 1) << 4);

#pragma unroll
        for (int ks = 0; ks < 8; ++ks) {
            const int jj = (ks << 3) + tig;
            const float es0 = es_sm[jj];
            const float es1 = es_sm[jj + 4];
            const u32 s0 = mAh >> (2 * ks);
            const u32 s1 = mBh >> (2 * ks);

            float l00 = ed0 + es0; l00 = fmaxf(l00, 0.2f * l00);
            float l10 = ed1 + es0; l10 = fmaxf(l10, 0.2f * l10);
            float l01 = ed0 + es1; l01 = fmaxf(l01, 0.2f * l01);
            float l11 = ed1 + es1; l11 = fmaxf(l11, 0.2f * l11);
            float p00 = (s0 & 1u) ? ex2f(l00) : 0.f;
            float p10 = (s1 & 1u) ? ex2f(l10) : 0.f;
            float p01 = (s0 & 2u) ? ex2f(l01) : 0.f;
            float p11 = (s1 & 2u) ? ex2f(l11) : 0.f;

            const u32 a0 = rnd_tf32(p00);
            const u32 a1 = rnd_tf32(p10);
            const u32 a2 = rnd_tf32(p01);
            const u32 a3 = rnd_tf32(p11);
            den0 += __uint_as_float(a0) + __uint_as_float(a2);
            den1 += __uint_as_float(a1) + __uint_as_float(a3);

            const uint4* hrow = hfrag + (ks << 7) + lane;
#pragma unroll
            for (int q = 0; q < 4; ++q) {
                uint4 bf = hrow[q << 5];
                mma16n8k8(acc[2 * q],     a0, a1, a2, a3, bf.x, bf.y);
                mma16n8k8(acc[2 * q + 1], a0, a1, a2, a3, bf.z, bf.w);
            }
        }
        __syncthreads();
        mA = nA; mB = nB;
    }

    den0 += __shfl_xor_sync(0xffffffffu, den0, 1);
    den0 += __shfl_xor_sync(0xffffffffu, den0, 2);
    den1 += __shfl_xor_sync(0xffffffffu, den1, 1);
    den1 += __shfl_xor_sync(0xffffffffu, den1, 2);
    if (tig == 0) {
        den_sm[i_w + grp] = den0;
        den_sm[i_w + 8 + grp] = den1;
    }
    __syncthreads();
    const float inv0 = 1.0f / den_sm[i_w + grp];
    const float inv1 = 1.0f / den_sm[i_w + 8 + grp];

    float* o0 = out + (size_t)(b * Nn + i0 + i_w + grp) * HF + h * 64;
    float* o1 = out + (size_t)(b * Nn + i0 + i_w + 8 + grp) * HF + h * 64;
#pragma unroll
    for (int n = 0; n < 8; ++n) {
        const int col = (n << 3) + (tig << 1);
        float2 bz = *(const float2*)&bias[h * 64 + col];
        float2 r0, r1;
        r0.x = acc[n][0] * inv0 + bz.x;  r0.y = acc[n][1] * inv0 + bz.y;
        r1.x = acc[n][2] * inv1 + bz.x;  r1.y = acc[n][3] * inv1 + bz.y;
        *(float2*)&o0[col] = r0;
        *(float2*)&o1[col] = r1;
    }
}

// ---------------------------------------------------------------------------
extern "C" void kernel_launch(void* const* d_in, const int* in_sizes, int n_in,
                              void* d_out, int out_size) {
    (void)in_sizes; (void)n_in; (void)out_size;
    const float* x     = (const float*)d_in[0];
    const float* adj   = (const float*)d_in[1];
    const float* W     = (const float*)d_in[2];
    const float* a_src = (const float*)d_in[3];
    const float* a_dst = (const float*)d_in[4];
    const float* bias  = (const float*)d_in[5];
    float* out = (float*)d_out;

    cudaFuncSetAttribute(attn_kernel,
                         cudaFuncAttributeMaxDynamicSharedMemorySize, SMEM_ATTN);

    mask_kernel<<<Mrows / 8, 256>>>(adj);
    gemm_fused<<<dim3(HF / 64, Mrows / 128), 256>>>(x, W, a_src, a_dst);
    attn_kernel<<<dim3(8, 64), 256, SMEM_ATTN>>>(bias, out);
}

// round 11
// speedup vs baseline: 1.8103x; 1.1777x over previous
#include <cuda_runtime.h>
#include <cstdint>

// BatchedGAT round 9:
//   wfrag_kernel: W -> tf32 B-fragments (one-time, 256KB).
//   gemm_mma:  h = x@W on mma.sync tf32; epilogue computes e_src/e_dst from
//              accumulator fragments and emits attn B-fragments (hs bounce
//              unioned with mainloop staging buffers). Replaces the 60us
//              fp32-FMA gemm.
//   attn:      R6's 99us flash-GAT kernel (adj cp.async staging) with
//              pre-scaled log2e e-arrays (FADD logits) and integer tf32
//              rounding. No mask kernel (R8 showed it was a net loss).

#define DEV __device__ __forceinline__
using u64 = unsigned long long;
using u32 = unsigned int;

DEV u32 cvt_tf32(float x) {
    u32 r; asm("cvt.rna.tf32.f32 %0, %1;" : "=r"(r) : "f"(x)); return r;
}
DEV float ex2f(float x) {
    float r; asm("ex2.approx.f32 %0, %1;" : "=f"(r) : "f"(x)); return r;
}
DEV u32 smem_u32(const void* p) {
    u32 a; asm("{ .reg .u64 t; cvta.to.shared.u64 t, %1; cvt.u32.u64 %0, t; }"
               : "=r"(a) : "l"(p));
    return a;
}
DEV void cpasync16(u32 dst, const void* src) {
    asm volatile("cp.async.cg.shared.global [%0], [%1], 16;"
                 :: "r"(dst), "l"(src) : "memory");
}
#define CP_COMMIT() asm volatile("cp.async.commit_group;" ::: "memory")
#define CP_WAIT1()  asm volatile("cp.async.wait_group 1;" ::: "memory")
#define CP_WAIT0()  asm volatile("cp.async.wait_group 0;" ::: "memory")

DEV void mma16n8k8(float* c, u32 a0, u32 a1, u32 a2, u32 a3, u32 b0, u32 b1) {
    asm volatile(
        "mma.sync.aligned.m16n8k8.row.col.f32.tf32.tf32.f32 "
        "{%0,%1,%2,%3}, {%4,%5,%6,%7}, {%8,%9}, {%0,%1,%2,%3};"
        : "+f"(c[0]), "+f"(c[1]), "+f"(c[2]), "+f"(c[3])
        : "r"(a0), "r"(a1), "r"(a2), "r"(a3), "r"(b0), "r"(b1));
}
// tf32 round-to-nearest (half-up) on fp32 bits; maps 0 -> 0. ALU-only.
DEV u32 rnd_tf32(float x) { return (__float_as_uint(x) + 0x1000u) & 0xFFFFE000u; }

constexpr int Bb = 16, Nn = 1024, Dd = 256, Hh = 4, HF = 256;
constexpr int Mrows = Bb * Nn;
constexpr float LOG2E = 1.4426950408889634f;

// e arrays transposed [h][b*N+n], PRE-SCALED by log2e.
__device__ float g_es[Hh * Mrows];
__device__ float g_ed[Hh * Mrows];
// attn B fragments: [bh][jb(128)][q(4)][lane(32)] uint4
__device__ uint4 g_hTf4[64 * 128 * 4 * 32];   // 16.8 MB
// W fragments: [bn(4)][k8(32)][nf(8)][lane(32)] uint2 (tf32 rna)
__device__ uint2 g_wf[4 * 32 * 8 * 32];       // 256 KB

// ---------------------------------------------------------------------------
// Kernel 0: W -> B-fragment layout (m16n8k8 col-major), tf32 rna.
// frag(bn,k8,nf)[lane] = ( W[k8*8+(lane&3)][bn*64+nf*8+(lane>>2)],
//                          W[k8*8+(lane&3)+4][same col] )
// ---------------------------------------------------------------------------
__global__ __launch_bounds__(256) void wfrag_kernel(const float* __restrict__ W) {
    const int bn = blockIdx.x;
    const int tid = threadIdx.x;
#pragma unroll
    for (int q = 0; q < 32; ++q) {
        int v = (q << 8) + tid;          // 0..8191
        int k8 = v >> 8;
        int nf = (v >> 5) & 7;
        int ln = v & 31;
        int k = (k8 << 3) + (ln & 3);
        int n = bn * 64 + (nf << 3) + (ln >> 2);
        uint2 o;
        o.x = cvt_tf32(__ldg(&W[k * HF + n]));
        o.y = cvt_tf32(__ldg(&W[(k + 4) * HF + n]));
        g_wf[((bn * 32 + k8) * 8 + nf) * 32 + ln] = o;
    }
}

// ---------------------------------------------------------------------------
// Kernel 1: gemm via mma.sync tf32 + fused e + attn-fragment emission.
// Grid (4 bn, 128 bm), 256 thr, 8 warps; warp w -> rows [16w,16w+16), 64 cols.
// K pipelined in 8 slabs of 32 (cp.async double buffer).
// ---------------------------------------------------------------------------
constexpr int XROW = 36;                 // padded floats per x row
constexpr int GOFF_X0 = 0;               // 128*36*4 = 18432
constexpr int GOFF_X1 = 18432;
constexpr int GOFF_WF0 = 36864;          // 8192
constexpr int GOFF_WF1 = 45056;
constexpr int SMEM_GEMM = 53248;         // hs[128][68] (34816) unioned at 0

__global__ __launch_bounds__(256) void gemm_mma(const float* __restrict__ A,
                                                const float* __restrict__ a_src,
                                                const float* __restrict__ a_dst) {
    extern __shared__ char gsm[];
    const u32 sbase = smem_u32(gsm);

    const int tid = threadIdx.x;
    const int w = tid >> 5, lane = tid & 31;
    const int bm = blockIdx.y, bn = blockIdx.x;
    const int i_w = w << 4;
    const int grp = lane >> 2;
    const int tig = lane & 3;

    const u32 x_off[2]  = { sbase + GOFF_X0,  sbase + GOFF_X1 };
    const u32 wf_off[2] = { sbase + GOFF_WF0, sbase + GOFF_WF1 };

    auto stage = [&](int s, int sel) {
        // x slab: 128 rows x 32 floats -> 1024 float4, 4 per thread
#pragma unroll
        for (int q = 0; q < 4; ++q) {
            int v = (q << 8) + tid;
            int row = v >> 3, c4 = (v & 7) << 2;
            cpasync16(x_off[sel] + (u32)(row * XROW + c4) * 4u,
                      A + (size_t)(bm * 128 + row) * Dd + (s << 5) + c4);
        }
        // W frags: 4 k8-steps = 8192B contiguous -> 512 uint4, 2 per thread
        const uint4* wsrc = (const uint4*)(g_wf + ((bn * 32 + (s << 2)) * 8) * 32);
#pragma unroll
        for (int q = 0; q < 2; ++q)
            cpasync16(wf_off[sel] + (u32)((q << 8) + tid) * 16u, wsrc + (q << 8) + tid);
    };

    float acc[8][4];
#pragma unroll
    for (int n = 0; n < 8; ++n)
#pragma unroll
        for (int k = 0; k < 4; ++k) acc[n][k] = 0.f;

    stage(0, 0); CP_COMMIT();

    for (int s = 0; s < 8; ++s) {
        const int sel = s & 1;
        if (s < 7) { stage(s + 1, sel ^ 1); CP_COMMIT(); }
        if (s < 7) CP_WAIT1(); else CP_WAIT0();
        __syncthreads();

        const float* xs = (const float*)(gsm + (sel ? GOFF_X1 : GOFF_X0));
        const uint2* wfs = (const uint2*)(gsm + (sel ? GOFF_WF1 : GOFF_WF0));

#pragma unroll
        for (int k8 = 0; k8 < 4; ++k8) {
            const int kc = (k8 << 3) + tig;
            u32 a0 = rnd_tf32(xs[(i_w + grp) * XROW + kc]);
            u32 a1 = rnd_tf32(xs[(i_w + 8 + grp) * XROW + kc]);
            u32 a2 = rnd_tf32(xs[(i_w + grp) * XROW + kc + 4]);
            u32 a3 = rnd_tf32(xs[(i_w + 8 + grp) * XROW + kc + 4]);
            const uint2* wr = wfs + (k8 << 8) + lane;
#pragma unroll
            for (int n = 0; n < 8; ++n) {
                uint2 bf = wr[n << 5];
                mma16n8k8(acc[n], a0, a1, a2, a3, bf.x, bf.y);
            }
        }
        __syncthreads();   // buf[sel] reads done before it is restaged
    }

    // ---- e_src/e_dst from accumulator fragments ----
    float ps0 = 0.f, ps1 = 0.f, pd0 = 0.f, pd1 = 0.f;
#pragma unroll
    for (int n = 0; n < 8; ++n) {
        float2 asv = *(const float2*)&a_src[bn * 64 + (n << 3) + (tig << 1)];
        float2 adv = *(const float2*)&a_dst[bn * 64 + (n << 3) + (tig << 1)];
        ps0 = fmaf(acc[n][0], asv.x, fmaf(acc[n][1], asv.y, ps0));
        ps1 = fmaf(acc[n][2], asv.x, fmaf(acc[n][3], asv.y, ps1));
        pd0 = fmaf(acc[n][0], adv.x, fmaf(acc[n][1], adv.y, pd0));
        pd1 = fmaf(acc[n][2], adv.x, fmaf(acc[n][3], adv.y, pd1));
    }
    ps0 += __shfl_xor_sync(0xffffffffu, ps0, 1);
    ps0 += __shfl_xor_sync(0xffffffffu, ps0, 2);
    ps1 += __shfl_xor_sync(0xffffffffu, ps1, 1);
    ps1 += __shfl_xor_sync(0xffffffffu, ps1, 2);
    pd0 += __shfl_xor_sync(0xffffffffu, pd0, 1);
    pd0 += __shfl_xor_sync(0xffffffffu, pd0, 2);
    pd1 += __shfl_xor_sync(0xffffffffu, pd1, 1);
    pd1 += __shfl_xor_sync(0xffffffffu, pd1, 2);
    if (tig == 0) {
        const int rg = bm * 128 + i_w + grp;
        g_es[bn * Mrows + rg]     = ps0 * LOG2E;
        g_es[bn * Mrows + rg + 8] = ps1 * LOG2E;
        g_ed[bn * Mrows + rg]     = pd0 * LOG2E;
        g_ed[bn * Mrows + rg + 8] = pd1 * LOG2E;
    }

    // ---- hs bounce (union with staging buffers) + fragment emission ----
    float (*hs)[68] = (float(*)[68])gsm;
    __syncthreads();   // staging buffers fully consumed
#pragma unroll
    for (int n = 0; n < 8; ++n) {
        const int col = (n << 3) + (tig << 1);
        hs[i_w + grp][col]         = acc[n][0];
        hs[i_w + grp][col + 1]     = acc[n][1];
        hs[i_w + 8 + grp][col]     = acc[n][2];
        hs[i_w + 8 + grp][col + 1] = acc[n][3];
    }
    __syncthreads();

    const int bh = (bm >> 3) * 4 + bn;
    const int jb0 = (bm & 7) * 16;
#pragma unroll
    for (int q2 = 0; q2 < 8; ++q2) {
        int v = (q2 << 8) + tid;
        int jbl = v >> 7;
        int q = (v >> 5) & 3;
        int ln = v & 31;
        int jl = jbl * 8 + (ln & 3);
        int f0 = (2 * q) * 8 + (ln >> 2);
        uint4 o;
        o.x = cvt_tf32(hs[jl][f0]);
        o.y = cvt_tf32(hs[jl + 4][f0]);
        o.z = cvt_tf32(hs[jl][f0 + 8]);
        o.w = cvt_tf32(hs[jl + 4][f0 + 8]);
        g_hTf4[(size_t)((bh * 128 + jb0 + jbl) * 4 + q) * 32 + ln] = o;
    }
}

// ---------------------------------------------------------------------------
// Kernel 2: flash-GAT attention (R6 structure: adj cp.async staging).
// ---------------------------------------------------------------------------
constexpr int ADJ_ST = 68;
constexpr int OFF_ADJ0 = 0;                    // 34816
constexpr int OFF_ADJ1 = 34816;
constexpr int OFF_HF0  = 69632;                // 16384
constexpr int OFF_HF1  = 86016;
constexpr int OFF_ES0  = 102400;
constexpr int OFF_ES1  = 102656;
constexpr int OFF_ED   = 102912;
constexpr int OFF_DEN  = 103424;
constexpr int SMEM_ATTN = 103936;

__global__ __launch_bounds__(256, 2) void attn_kernel(const float* __restrict__ adj,
                                                      const float* __restrict__ bias,
                                                      float* __restrict__ out) {
    extern __shared__ char dsm[];
    const u32 sbase = smem_u32(dsm);
    float* ed_sm  = (float*)(dsm + OFF_ED);
    float* den_sm = (float*)(dsm + OFF_DEN);

    const int tid = threadIdx.x;
    const int w = tid >> 5, lane = tid & 31;
    const int bh = blockIdx.y, b = bh >> 2, h = bh & 3;
    const int i0 = blockIdx.x << 7;
    const int i_w = w << 4;
    const int grp = lane >> 2;
    const int tig = lane & 3;

    const u32 adj_off[2] = { sbase + OFF_ADJ0, sbase + OFF_ADJ1 };
    const u32 hf_off[2]  = { sbase + OFF_HF0,  sbase + OFF_HF1 };
    const u32 es_off[2]  = { sbase + OFF_ES0,  sbase + OFF_ES1 };

    const float* adj_base = adj + (size_t)(b * Nn + i0) * Nn;
    const uint4* hf_base = g_hTf4 + (size_t)bh * 128 * 4 * 32;
    const float* es_base = g_es + h * Mrows + b * Nn;

    auto stage = [&](int jt, int sel) {
        const int j0 = jt << 6;
        const int r = tid >> 4, c4 = (tid & 15) << 2;
#pragma unroll
        for (int q = 0; q < 8; ++q)
            cpasync16(adj_off[sel] + (u32)(((q << 4) + r) * ADJ_ST + c4) * 4u,
                      adj_base + (size_t)((q << 4) + r) * Nn + j0 + c4);
        const uint4* hs = hf_base + (size_t)(jt * 8) * 4 * 32;
#pragma unroll
        for (int q = 0; q < 4; ++q)
            cpasync16(hf_off[sel] + (u32)((q << 8) + tid) * 16u, hs + (q << 8) + tid);
        if (tid < 16)
            cpasync16(es_off[sel] + (u32)tid * 16u, es_base + j0 + tid * 4);
    };

    stage(0, 0); CP_COMMIT();
    if (tid < 128) ed_sm[tid] = g_ed[h * Mrows + b * Nn + i0 + tid];

    float acc[8][4];
#pragma unroll
    for (int n = 0; n < 8; ++n)
#pragma unroll
        for (int k = 0; k < 4; ++k) acc[n][k] = 0.f;
    float den0 = 0.f, den1 = 0.f;

    __syncthreads();
    const float ed0 = ed_sm[i_w + grp];
    const float ed1 = ed_sm[i_w + 8 + grp];

    for (int jt = 0; jt < 16; ++jt) {
        const int sel = jt & 1;
        if (jt < 15) { stage(jt + 1, sel ^ 1); CP_COMMIT(); }
        if (jt < 15) CP_WAIT1(); else CP_WAIT0();
        __syncthreads();

        const float* adj_sm = (const float*)(dsm + (sel ? OFF_ADJ1 : OFF_ADJ0));
        const uint4* hfrag  = (const uint4*)(dsm + (sel ? OFF_HF1 : OFF_HF0));
        const float* es_sm  = (const float*)(dsm + (sel ? OFF_ES1 : OFF_ES0));

#pragma unroll
        for (int ks = 0; ks < 8; ++ks) {
            const int jj = (ks << 3) + tig;
            const float es0 = es_sm[jj];
            const float es1 = es_sm[jj + 4];

            float l00 = ed0 + es0; l00 = fmaxf(l00, 0.2f * l00);
            float l10 = ed1 + es0; l10 = fmaxf(l10, 0.2f * l10);
            float l01 = ed0 + es1; l01 = fmaxf(l01, 0.2f * l01);
            float l11 = ed1 + es1; l11 = fmaxf(l11, 0.2f * l11);
            float p00 = (adj_sm[(i_w + grp) * ADJ_ST + jj]          > 0.5f) ? ex2f(l00) : 0.f;
            float p10 = (adj_sm[(i_w + 8 + grp) * ADJ_ST + jj]      > 0.5f) ? ex2f(l10) : 0.f;
            float p01 = (adj_sm[(i_w + grp) * ADJ_ST + jj + 4]      > 0.5f) ? ex2f(l01) : 0.f;
            float p11 = (adj_sm[(i_w + 8 + grp) * ADJ_ST + jj + 4]  > 0.5f) ? ex2f(l11) : 0.f;

            const u32 a0 = rnd_tf32(p00);
            const u32 a1 = rnd_tf32(p10);
            const u32 a2 = rnd_tf32(p01);
            const u32 a3 = rnd_tf32(p11);
            den0 += __uint_as_float(a0) + __uint_as_float(a2);
            den1 += __uint_as_float(a1) + __uint_as_float(a3);

            const uint4* hrow = hfrag + (ks << 7) + lane;
#pragma unroll
            for (int q = 0; q < 4; ++q) {
                uint4 bf = hrow[q << 5];
                mma16n8k8(acc[2 * q],     a0, a1, a2, a3, bf.x, bf.y);
                mma16n8k8(acc[2 * q + 1], a0, a1, a2, a3, bf.z, bf.w);
            }
        }
        __syncthreads();
    }

    den0 += __shfl_xor_sync(0xffffffffu, den0, 1);
    den0 += __shfl_xor_sync(0xffffffffu, den0, 2);
    den1 += __shfl_xor_sync(0xffffffffu, den1, 1);
    den1 += __shfl_xor_sync(0xffffffffu, den1, 2);
    if (tig == 0) {
        den_sm[i_w + grp] = den0;
        den_sm[i_w + 8 + grp] = den1;
    }
    __syncthreads();
    const float inv0 = 1.0f / den_sm[i_w + grp];
    const float inv1 = 1.0f / den_sm[i_w + 8 + grp];

    float* o0 = out + (size_t)(b * Nn + i0 + i_w + grp) * HF + h * 64;
    float* o1 = out + (size_t)(b * Nn + i0 + i_w + 8 + grp) * HF + h * 64;
#pragma unroll
    for (int n = 0; n < 8; ++n) {
        const int col = (n << 3) + (tig << 1);
        float2 bz = *(const float2*)&bias[h * 64 + col];
        float2 r0, r1;
        r0.x = acc[n][0] * inv0 + bz.x;  r0.y = acc[n][1] * inv0 + bz.y;
        r1.x = acc[n][2] * inv1 + bz.x;  r1.y = acc[n][3] * inv1 + bz.y;
        *(float2*)&o0[col] = r0;
        *(float2*)&o1[col] = r1;
    }
}

// ---------------------------------------------------------------------------
extern "C" void kernel_launch(void* const* d_in, const int* in_sizes, int n_in,
                              void* d_out, int out_size) {
    (void)in_sizes; (void)n_in; (void)out_size;
    const float* x     = (const float*)d_in[0];
    const float* adj   = (const float*)d_in[1];
    const float* W     = (const float*)d_in[2];
    const float* a_src = (const float*)d_in[3];
    const float* a_dst = (const float*)d_in[4];
    const float* bias  = (const float*)d_in[5];
    float* out = (float*)d_out;

    cudaFuncSetAttribute(gemm_mma,
                         cudaFuncAttributeMaxDynamicSharedMemorySize, SMEM_GEMM);
    cudaFuncSetAttribute(attn_kernel,
                         cudaFuncAttributeMaxDynamicSharedMemorySize, SMEM_ATTN);

    wfrag_kernel<<<4, 256>>>(W);
    gemm_mma<<<dim3(4, 128), 256, SMEM_GEMM>>>(x, a_src, a_dst);
    attn_kernel<<<dim3(8, 64), 256, SMEM_ATTN>>>(adj, bias, out);
}

// round 12
// speedup vs baseline: 1.8866x; 1.0421x over previous
#include <cuda_runtime.h>
#include <cstdint>

// BatchedGAT round 11:
//   wfrag_kernel: W -> tf32 B-fragments (grid 32, was 4 -> latency fix).
//   gemm_mma: h = x@W on mma.sync tf32. ONE CTA per 128-row block covers all
//             4 heads (512 thr, 16 warps, warp = 2 m-tiles x 64 cols):
//             x staged once (kills 4x redundant x traffic of R9), W-frags for
//             all heads staged per K-slab. e_src/e_dst fully warp-local.
//             Epilogue emits attn B-fragments per head via unioned hs bounce.
//   attn: unchanged from R9 (best-known 99us flash-GAT, mma.sync tf32).

#define DEV __device__ __forceinline__
using u64 = unsigned long long;
using u32 = unsigned int;

DEV u32 cvt_tf32(float x) {
    u32 r; asm("cvt.rna.tf32.f32 %0, %1;" : "=r"(r) : "f"(x)); return r;
}
DEV float ex2f(float x) {
    float r; asm("ex2.approx.f32 %0, %1;" : "=f"(r) : "f"(x)); return r;
}
DEV u32 smem_u32(const void* p) {
    u32 a; asm("{ .reg .u64 t; cvta.to.shared.u64 t, %1; cvt.u32.u64 %0, t; }"
               : "=r"(a) : "l"(p));
    return a;
}
DEV void cpasync16(u32 dst, const void* src) {
    asm volatile("cp.async.cg.shared.global [%0], [%1], 16;"
                 :: "r"(dst), "l"(src) : "memory");
}
#define CP_COMMIT() asm volatile("cp.async.commit_group;" ::: "memory")
#define CP_WAIT1()  asm volatile("cp.async.wait_group 1;" ::: "memory")
#define CP_WAIT0()  asm volatile("cp.async.wait_group 0;" ::: "memory")

DEV void mma16n8k8(float* c, u32 a0, u32 a1, u32 a2, u32 a3, u32 b0, u32 b1) {
    asm volatile(
        "mma.sync.aligned.m16n8k8.row.col.f32.tf32.tf32.f32 "
        "{%0,%1,%2,%3}, {%4,%5,%6,%7}, {%8,%9}, {%0,%1,%2,%3};"
        : "+f"(c[0]), "+f"(c[1]), "+f"(c[2]), "+f"(c[3])
        : "r"(a0), "r"(a1), "r"(a2), "r"(a3), "r"(b0), "r"(b1));
}
// tf32 round-to-nearest (half-up) on fp32 bits; maps 0 -> 0. ALU-only.
DEV u32 rnd_tf32(float x) { return (__float_as_uint(x) + 0x1000u) & 0xFFFFE000u; }

constexpr int Bb = 16, Nn = 1024, Dd = 256, Hh = 4, HF = 256;
constexpr int Mrows = Bb * Nn;
constexpr float LOG2E = 1.4426950408889634f;

// e arrays transposed [h][b*N+n], PRE-SCALED by log2e.
__device__ float g_es[Hh * Mrows];
__device__ float g_ed[Hh * Mrows];
// attn B fragments: [bh][jb(128)][q(4)][lane(32)] uint4
__device__ uint4 g_hTf4[64 * 128 * 4 * 32];   // 16.8 MB
// W fragments: [bn(4)][k8(32)][nf(8)][lane(32)] uint2 (tf32 rna)
__device__ uint2 g_wf[4 * 32 * 8 * 32];       // 256 KB

// ---------------------------------------------------------------------------
// Kernel 0: W -> B-fragment layout (m16n8k8 col-major), tf32 rna.
// ---------------------------------------------------------------------------
__global__ __launch_bounds__(256) void wfrag_kernel(const float* __restrict__ W) {
    const int tid = threadIdx.x;
    const int blk = blockIdx.x;           // 0..31
#pragma unroll
    for (int q = 0; q < 4; ++q) {
        int v = blk * 1024 + (q << 8) + tid;   // 0..32767
        int bn = v >> 13;
        int k8 = (v >> 8) & 31;
        int nf = (v >> 5) & 7;
        int ln = v & 31;
        int k = (k8 << 3) + (ln & 3);
        int n = bn * 64 + (nf << 3) + (ln >> 2);
        uint2 o;
        o.x = cvt_tf32(__ldg(&W[k * HF + n]));
        o.y = cvt_tf32(__ldg(&W[(k + 4) * HF + n]));
        g_wf[((bn * 32 + k8) * 8 + nf) * 32 + ln] = o;
    }
}

// ---------------------------------------------------------------------------
// Kernel 1: gemm via mma.sync tf32 + fused e + attn-fragment emission.
// Grid 128 (bm), 512 thr, 16 warps. Warp w: rg=w>>2, cg=w&3.
//   rows: {rg*16..+15, 64+rg*16..+15}, cols: cg*64..+63 (head cg).
// K pipelined in 8 slabs of 32 (cp.async double buffer).
// ---------------------------------------------------------------------------
constexpr int XROW = 36;                  // padded floats per x row (4grp+tig banks)
constexpr int GOFF_X0  = 0;               // 128*36*4 = 18432
constexpr int GOFF_X1  = 18432;
constexpr int GOFF_WF0 = 36864;           // 32768 (all 4 heads, 4 k8 steps)
constexpr int GOFF_WF1 = 69632;
constexpr int SMEM_GEMM = 102400;         // hs[128][68] (34816) unioned at 0

__global__ __launch_bounds__(512) void gemm_mma(const float* __restrict__ A,
                                                const float* __restrict__ a_src,
                                                const float* __restrict__ a_dst) {
    extern __shared__ char gsm[];
    const u32 sbase = smem_u32(gsm);

    const int tid = threadIdx.x;
    const int w = tid >> 5, lane = tid & 31;
    const int bm = blockIdx.x;
    const int rg = w >> 2, cg = w & 3;
    const int grp = lane >> 2;
    const int tig = lane & 3;
    const int r0 = rg * 16;               // tile0 rows r0..r0+15; tile1 rows 64+r0..

    const u32 x_off[2]  = { sbase + GOFF_X0,  sbase + GOFF_X1 };
    const u32 wf_off[2] = { sbase + GOFF_WF0, sbase + GOFF_WF1 };

    auto stage = [&](int s, int sel) {
        // x slab: 128 rows x 32 floats -> 1024 float4, 2 per thread
#pragma unroll
        for (int q = 0; q < 2; ++q) {
            int v = (q << 9) + tid;
            int row = v >> 3, c4 = (v & 7) << 2;
            cpasync16(x_off[sel] + (u32)(row * XROW + c4) * 4u,
                      A + (size_t)(bm * 128 + row) * Dd + (s << 5) + c4);
        }
        // W frags: 4 heads x 4 k8 steps = 32KB -> 2048 uint4, 4 per thread
#pragma unroll
        for (int q = 0; q < 4; ++q) {
            int v = (q << 9) + tid;       // 0..2047
            int bn = v >> 9;
            int rest = v & 511;           // uint4 within 8KB chunk
            const uint4* src = (const uint4*)(g_wf + (size_t)((bn * 32 + (s << 2)) * 8) * 32) + rest;
            cpasync16(wf_off[sel] + (u32)((bn * 512 + rest)) * 16u, src);
        }
    };

    float acc0[8][4], acc1[8][4];
#pragma unroll
    for (int n = 0; n < 8; ++n)
#pragma unroll
        for (int k = 0; k < 4; ++k) { acc0[n][k] = 0.f; acc1[n][k] = 0.f; }

    stage(0, 0); CP_COMMIT();

    for (int s = 0; s < 8; ++s) {
        const int sel = s & 1;
        if (s < 7) { stage(s + 1, sel ^ 1); CP_COMMIT(); }
        if (s < 7) CP_WAIT1(); else CP_WAIT0();
        __syncthreads();

        const float* xs = (const float*)(gsm + (sel ? GOFF_X1 : GOFF_X0));
        const uint2* wfs = (const uint2*)(gsm + (sel ? GOFF_WF1 : GOFF_WF0));

#pragma unroll
        for (int k8 = 0; k8 < 4; ++k8) {
            const int kc = (k8 << 3) + tig;
            u32 a0 = rnd_tf32(xs[(r0 + grp) * XROW + kc]);
            u32 a1 = rnd_tf32(xs[(r0 + 8 + grp) * XROW + kc]);
            u32 a2 = rnd_tf32(xs[(r0 + grp) * XROW + kc + 4]);
            u32 a3 = rnd_tf32(xs[(r0 + 8 + grp) * XROW + kc + 4]);
            u32 a4 = rnd_tf32(xs[(64 + r0 + grp) * XROW + kc]);
            u32 a5 = rnd_tf32(xs[(64 + r0 + 8 + grp) * XROW + kc]);
            u32 a6 = rnd_tf32(xs[(64 + r0 + grp) * XROW + kc + 4]);
            u32 a7 = rnd_tf32(xs[(64 + r0 + 8 + grp) * XROW + kc + 4]);
            const uint2* wr = wfs + ((cg * 4 + k8) << 8) + lane;
#pragma unroll
            for (int n = 0; n < 8; ++n) {
                uint2 bf = wr[n << 5];
                mma16n8k8(acc0[n], a0, a1, a2, a3, bf.x, bf.y);
                mma16n8k8(acc1[n], a4, a5, a6, a7, bf.x, bf.y);
            }
        }
        __syncthreads();   // buf[sel] reads done before restage
    }

    // ---- e_src/e_dst: warp-local (cols == head cg) ----
    {
        float ps0 = 0.f, ps1 = 0.f, pd0 = 0.f, pd1 = 0.f;   // tile0
        float qs0 = 0.f, qs1 = 0.f, qd0 = 0.f, qd1 = 0.f;   // tile1
#pragma unroll
        for (int n = 0; n < 8; ++n) {
            float2 asv = *(const float2*)&a_src[cg * 64 + (n << 3) + (tig << 1)];
            float2 adv = *(const float2*)&a_dst[cg * 64 + (n << 3) + (tig << 1)];
            ps0 = fmaf(acc0[n][0], asv.x, fmaf(acc0[n][1], asv.y, ps0));
            ps1 = fmaf(acc0[n][2], asv.x, fmaf(acc0[n][3], asv.y, ps1));
            pd0 = fmaf(acc0[n][0], adv.x, fmaf(acc0[n][1], adv.y, pd0));
            pd1 = fmaf(acc0[n][2], adv.x, fmaf(acc0[n][3], adv.y, pd1));
            qs0 = fmaf(acc1[n][0], asv.x, fmaf(acc1[n][1], asv.y, qs0));
            qs1 = fmaf(acc1[n][2], asv.x, fmaf(acc1[n][3], asv.y, qs1));
            qd0 = fmaf(acc1[n][0], adv.x, fmaf(acc1[n][1], adv.y, qd0));
            qd1 = fmaf(acc1[n][2], adv.x, fmaf(acc1[n][3], adv.y, qd1));
        }
#pragma unroll
        for (int o = 1; o < 4; o <<= 1) {
            ps0 += __shfl_xor_sync(0xffffffffu, ps0, o);
            ps1 += __shfl_xor_sync(0xffffffffu, ps1, o);
            pd0 += __shfl_xor_sync(0xffffffffu, pd0, o);
            pd1 += __shfl_xor_sync(0xffffffffu, pd1, o);
            qs0 += __shfl_xor_sync(0xffffffffu, qs0, o);
            qs1 += __shfl_xor_sync(0xffffffffu, qs1, o);
            qd0 += __shfl_xor_sync(0xffffffffu, qd0, o);
            qd1 += __shfl_xor_sync(0xffffffffu, qd1, o);
        }
        if (tig == 0) {
            const int base = cg * Mrows + bm * 128;
            g_es[base + r0 + grp]           = ps0 * LOG2E;
            g_es[base + r0 + 8 + grp]       = ps1 * LOG2E;
            g_ed[base + r0 + grp]           = pd0 * LOG2E;
            g_ed[base + r0 + 8 + grp]       = pd1 * LOG2E;
            g_es[base + 64 + r0 + grp]      = qs0 * LOG2E;
            g_es[base + 64 + r0 + 8 + grp]  = qs1 * LOG2E;
            g_ed[base + 64 + r0 + grp]      = qd0 * LOG2E;
            g_ed[base + 64 + r0 + 8 + grp]  = qd1 * LOG2E;
        }
    }

    // ---- per-head hs bounce + fragment emission ----
    float (*hs)[68] = (float(*)[68])gsm;
    const int b_ = bm >> 3;
    const int jb0 = (bm & 7) * 16;

    for (int hh = 0; hh < 4; ++hh) {
        __syncthreads();                  // previous use of region done
        if (cg == hh) {
#pragma unroll
            for (int n = 0; n < 8; ++n) {
                const int col = (n << 3) + (tig << 1);
                hs[r0 + grp][col]          = acc0[n][0];
                hs[r0 + grp][col + 1]      = acc0[n][1];
                hs[r0 + 8 + grp][col]      = acc0[n][2];
                hs[r0 + 8 + grp][col + 1]  = acc0[n][3];
                hs[64 + r0 + grp][col]         = acc1[n][0];
                hs[64 + r0 + grp][col + 1]     = acc1[n][1];
                hs[64 + r0 + 8 + grp][col]     = acc1[n][2];
                hs[64 + r0 + 8 + grp][col + 1] = acc1[n][3];
            }
        }
        __syncthreads();

        const int bh = b_ * 4 + hh;
#pragma unroll
        for (int q2 = 0; q2 < 4; ++q2) {
            int v = (q2 << 9) + tid;      // 0..2047
            int jbl = v >> 7;
            int q = (v >> 5) & 3;
            int ln = v & 31;
            int jl = jbl * 8 + (ln & 3);
            int f0 = (2 * q) * 8 + (ln >> 2);
            uint4 o;
            o.x = cvt_tf32(hs[jl][f0]);
            o.y = cvt_tf32(hs[jl + 4][f0]);
            o.z = cvt_tf32(hs[jl][f0 + 8]);
            o.w = cvt_tf32(hs[jl + 4][f0 + 8]);
            g_hTf4[(size_t)((bh * 128 + jb0 + jbl) * 4 + q) * 32 + ln] = o;
        }
    }
}

// ---------------------------------------------------------------------------
// Kernel 2: flash-GAT attention (unchanged from R9).
// ---------------------------------------------------------------------------
constexpr int ADJ_ST = 68;
constexpr int OFF_ADJ0 = 0;
constexpr int OFF_ADJ1 = 34816;
constexpr int OFF_HF0  = 69632;
constexpr int OFF_HF1  = 86016;
constexpr int OFF_ES0  = 102400;
constexpr int OFF_ES1  = 102656;
constexpr int OFF_ED   = 102912;
constexpr int OFF_DEN  = 103424;
constexpr int SMEM_ATTN = 103936;

__global__ __launch_bounds__(256, 2) void attn_kernel(const float* __restrict__ adj,
                                                      const float* __restrict__ bias,
                                                      float* __restrict__ out) {
    extern __shared__ char dsm[];
    const u32 sbase = smem_u32(dsm);
    float* ed_sm  = (float*)(dsm + OFF_ED);
    float* den_sm = (float*)(dsm + OFF_DEN);

    const int tid = threadIdx.x;
    const int w = tid >> 5, lane = tid & 31;
    const int bh = blockIdx.y, b = bh >> 2, h = bh & 3;
    const int i0 = blockIdx.x << 7;
    const int i_w = w << 4;
    const int grp = lane >> 2;
    const int tig = lane & 3;

    const u32 adj_off[2] = { sbase + OFF_ADJ0, sbase + OFF_ADJ1 };
    const u32 hf_off[2]  = { sbase + OFF_HF0,  sbase + OFF_HF1 };
    const u32 es_off[2]  = { sbase + OFF_ES0,  sbase + OFF_ES1 };

    const float* adj_base = adj + (size_t)(b * Nn + i0) * Nn;
    const uint4* hf_base = g_hTf4 + (size_t)bh * 128 * 4 * 32;
    const float* es_base = g_es + h * Mrows + b * Nn;

    auto stage = [&](int jt, int sel) {
        const int j0 = jt << 6;
        const int r = tid >> 4, c4 = (tid & 15) << 2;
#pragma unroll
        for (int q = 0; q < 8; ++q)
            cpasync16(adj_off[sel] + (u32)(((q << 4) + r) * ADJ_ST + c4) * 4u,
                      adj_base + (size_t)((q << 4) + r) * Nn + j0 + c4);
        const uint4* hs = hf_base + (size_t)(jt * 8) * 4 * 32;
#pragma unroll
        for (int q = 0; q < 4; ++q)
            cpasync16(hf_off[sel] + (u32)((q << 8) + tid) * 16u, hs + (q << 8) + tid);
        if (tid < 16)
            cpasync16(es_off[sel] + (u32)tid * 16u, es_base + j0 + tid * 4);
    };

    stage(0, 0); CP_COMMIT();
    if (tid < 128) ed_sm[tid] = g_ed[h * Mrows + b * Nn + i0 + tid];

    float acc[8][4];
#pragma unroll
    for (int n = 0; n < 8; ++n)
#pragma unroll
        for (int k = 0; k < 4; ++k) acc[n][k] = 0.f;
    float den0 = 0.f, den1 = 0.f;

    __syncthreads();
    const float ed0 = ed_sm[i_w + grp];
    const float ed1 = ed_sm[i_w + 8 + grp];

    for (int jt = 0; jt < 16; ++jt) {
        const int sel = jt & 1;
        if (jt < 15) { stage(jt + 1, sel ^ 1); CP_COMMIT(); }
        if (jt < 15) CP_WAIT1(); else CP_WAIT0();
        __syncthreads();

        const float* adj_sm = (const float*)(dsm + (sel ? OFF_ADJ1 : OFF_ADJ0));
        const uint4* hfrag  = (const uint4*)(dsm + (sel ? OFF_HF1 : OFF_HF0));
        const float* es_sm  = (const float*)(dsm + (sel ? OFF_ES1 : OFF_ES0));

#pragma unroll
        for (int ks = 0; ks < 8; ++ks) {
            const int jj = (ks << 3) + tig;
            const float es0 = es_sm[jj];
            const float es1 = es_sm[jj + 4];

            float l00 = ed0 + es0; l00 = fmaxf(l00, 0.2f * l00);
            float l10 = ed1 + es0; l10 = fmaxf(l10, 0.2f * l10);
            float l01 = ed0 + es1; l01 = fmaxf(l01, 0.2f * l01);
            float l11 = ed1 + es1; l11 = fmaxf(l11, 0.2f * l11);
            float p00 = (adj_sm[(i_w + grp) * ADJ_ST + jj]          > 0.5f) ? ex2f(l00) : 0.f;
            float p10 = (adj_sm[(i_w + 8 + grp) * ADJ_ST + jj]      > 0.5f) ? ex2f(l10) : 0.f;
            float p01 = (adj_sm[(i_w + grp) * ADJ_ST + jj + 4]      > 0.5f) ? ex2f(l01) : 0.f;
            float p11 = (adj_sm[(i_w + 8 + grp) * ADJ_ST + jj + 4]  > 0.5f) ? ex2f(l11) : 0.f;

            const u32 a0 = rnd_tf32(p00);
            const u32 a1 = rnd_tf32(p10);
            const u32 a2 = rnd_tf32(p01);
            const u32 a3 = rnd_tf32(p11);
            den0 += __uint_as_float(a0) + __uint_as_float(a2);
            den1 += __uint_as_float(a1) + __uint_as_float(a3);

            const uint4* hrow = hfrag + (ks << 7) + lane;
#pragma unroll
            for (int q = 0; q < 4; ++q) {
                uint4 bf = hrow[q << 5];
                mma16n8k8(acc[2 * q],     a0, a1, a2, a3, bf.x, bf.y);
                mma16n8k8(acc[2 * q + 1], a0, a1, a2, a3, bf.z, bf.w);
            }
        }
        __syncthreads();
    }

    den0 += __shfl_xor_sync(0xffffffffu, den0, 1);
    den0 += __shfl_xor_sync(0xffffffffu, den0, 2);
    den1 += __shfl_xor_sync(0xffffffffu, den1, 1);
    den1 += __shfl_xor_sync(0xffffffffu, den1, 2);
    if (tig == 0) {
        den_sm[i_w + grp] = den0;
        den_sm[i_w + 8 + grp] = den1;
    }
    __syncthreads();
    const float inv0 = 1.0f / den_sm[i_w + grp];
    const float inv1 = 1.0f / den_sm[i_w + 8 + grp];

    float* o0 = out + (size_t)(b * Nn + i0 + i_w + grp) * HF + h * 64;
    float* o1 = out + (size_t)(b * Nn + i0 + i_w + 8 + grp) * HF + h * 64;
#pragma unroll
    for (int n = 0; n < 8; ++n) {
        const int col = (n << 3) + (tig << 1);
        float2 bz = *(const float2*)&bias[h * 64 + col];
        float2 r0, r1;
        r0.x = acc[n][0] * inv0 + bz.x;  r0.y = acc[n][1] * inv0 + bz.y;
        r1.x = acc[n][2] * inv1 + bz.x;  r1.y = acc[n][3] * inv1 + bz.y;
        *(float2*)&o0[col] = r0;
        *(float2*)&o1[col] = r1;
    }
}

// ---------------------------------------------------------------------------
extern "C" void kernel_launch(void* const* d_in, const int* in_sizes, int n_in,
                              void* d_out, int out_size) {
    (void)in_sizes; (void)n_in; (void)out_size;
    const float* x     = (const float*)d_in[0];
    const float* adj   = (const float*)d_in[1];
    const float* W     = (const float*)d_in[2];
    const float* a_src = (const float*)d_in[3];
    const float* a_dst = (const float*)d_in[4];
    const float* bias  = (const float*)d_in[5];
    float* out = (float*)d_out;

    cudaFuncSetAttribute(gemm_mma,
                         cudaFuncAttributeMaxDynamicSharedMemorySize, SMEM_GEMM);
    cudaFuncSetAttribute(attn_kernel,
                         cudaFuncAttributeMaxDynamicSharedMemorySize, SMEM_ATTN);

    wfrag_kernel<<<32, 256>>>(W);
    gemm_mma<<<128, 512, SMEM_GEMM>>>(x, a_src, a_dst);
    attn_kernel<<<dim3(8, 64), 256, SMEM_ATTN>>>(adj, bias, out);
}

// round 14
// speedup vs baseline: 2.8554x; 1.5135x over previous
#include <cuda_runtime.h>
#include <cstdint>

// BatchedGAT round 13:
//   wfrag_kernel: W -> tf32 B-fragments (unchanged).
//   gemm_mma: h = x@W on mma.sync tf32 (unchanged); epilogue emits attn
//             B-fragments as FP16x2 pairs for m16n8k16.
//   attn: flash-GAT aggregation on fp16 m16n8k16 (R13's bf16 failed at
//         1.3e-3 rel_err; fp16 has 8x finer mantissa -> predicted ~4e-4).
//         Denominator = exact fp32 sum of unrounded p.

#define DEV __device__ __forceinline__
using u64 = unsigned long long;
using u32 = unsigned int;

DEV u32 cvt_tf32(float x) {
    u32 r; asm("cvt.rna.tf32.f32 %0, %1;" : "=r"(r) : "f"(x)); return r;
}
DEV float ex2f(float x) {
    float r; asm("ex2.approx.f32 %0, %1;" : "=f"(r) : "f"(x)); return r;
}
// pack {lo, hi} floats -> f16x2 (lo in low half)
DEV u32 packhf(float lo, float hi) {
    u32 r; asm("cvt.rn.f16x2.f32 %0, %1, %2;" : "=r"(r) : "f"(hi), "f"(lo));
    return r;
}
DEV u32 smem_u32(const void* p) {
    u32 a; asm("{ .reg .u64 t; cvta.to.shared.u64 t, %1; cvt.u32.u64 %0, t; }"
               : "=r"(a) : "l"(p));
    return a;
}
DEV void cpasync16(u32 dst, const void* src) {
    asm volatile("cp.async.cg.shared.global [%0], [%1], 16;"
                 :: "r"(dst), "l"(src) : "memory");
}
#define CP_COMMIT() asm volatile("cp.async.commit_group;" ::: "memory")
#define CP_WAIT1()  asm volatile("cp.async.wait_group 1;" ::: "memory")
#define CP_WAIT0()  asm volatile("cp.async.wait_group 0;" ::: "memory")

DEV void mma16n8k8(float* c, u32 a0, u32 a1, u32 a2, u32 a3, u32 b0, u32 b1) {
    asm volatile(
        "mma.sync.aligned.m16n8k8.row.col.f32.tf32.tf32.f32 "
        "{%0,%1,%2,%3}, {%4,%5,%6,%7}, {%8,%9}, {%0,%1,%2,%3};"
        : "+f"(c[0]), "+f"(c[1]), "+f"(c[2]), "+f"(c[3])
        : "r"(a0), "r"(a1), "r"(a2), "r"(a3), "r"(b0), "r"(b1));
}
DEV void mma16n8k16hf(float* c, u32 a0, u32 a1, u32 a2, u32 a3, u32 b0, u32 b1) {
    asm volatile(
        "mma.sync.aligned.m16n8k16.row.col.f32.f16.f16.f32 "
        "{%0,%1,%2,%3}, {%4,%5,%6,%7}, {%8,%9}, {%0,%1,%2,%3};"
        : "+f"(c[0]), "+f"(c[1]), "+f"(c[2]), "+f"(c[3])
        : "r"(a0), "r"(a1), "r"(a2), "r"(a3), "r"(b0), "r"(b1));
}
// tf32 round-to-nearest (half-up) on fp32 bits (gemm A-path only).
DEV u32 rnd_tf32(float x) { return (__float_as_uint(x) + 0x1000u) & 0xFFFFE000u; }

constexpr int Bb = 16, Nn = 1024, Dd = 256, Hh = 4, HF = 256;
constexpr int Mrows = Bb * Nn;
constexpr float LOG2E = 1.4426950408889634f;

// e arrays transposed [h][b*N+n], PRE-SCALED by log2e.
__device__ float g_es[Hh * Mrows];
__device__ float g_ed[Hh * Mrows];
// attn B fragments (fp16 m16n8k16): [bh][jb16(64)][nf(8)][lane(32)] uint2
__device__ uint2 g_hBf[64 * 64 * 8 * 32];     // 8.4 MB
// W fragments (tf32 m16n8k8): [bn(4)][k8(32)][nf(8)][lane(32)] uint2
__device__ uint2 g_wf[4 * 32 * 8 * 32];       // 256 KB

// ---------------------------------------------------------------------------
// Kernel 0: W -> tf32 B-fragment layout (m16n8k8 col-major).
// ---------------------------------------------------------------------------
__global__ __launch_bounds__(256) void wfrag_kernel(const float* __restrict__ W) {
    const int tid = threadIdx.x;
    const int blk = blockIdx.x;           // 0..31
#pragma unroll
    for (int q = 0; q < 4; ++q) {
        int v = blk * 1024 + (q << 8) + tid;   // 0..32767
        int bn = v >> 13;
        int k8 = (v >> 8) & 31;
        int nf = (v >> 5) & 7;
        int ln = v & 31;
        int k = (k8 << 3) + (ln & 3);
        int n = bn * 64 + (nf << 3) + (ln >> 2);
        uint2 o;
        o.x = cvt_tf32(__ldg(&W[k * HF + n]));
        o.y = cvt_tf32(__ldg(&W[(k + 4) * HF + n]));
        g_wf[((bn * 32 + k8) * 8 + nf) * 32 + ln] = o;
    }
}

// ---------------------------------------------------------------------------
// Kernel 1: gemm via mma.sync tf32 + fused e + fp16 attn-fragment emission.
// Grid 128 (bm), 512 thr, 16 warps. Warp w: rg=w>>2, cg=w&3.
// ---------------------------------------------------------------------------
constexpr int XROW = 36;
constexpr int GOFF_X0  = 0;               // 18432
constexpr int GOFF_X1  = 18432;
constexpr int GOFF_WF0 = 36864;           // 32768
constexpr int GOFF_WF1 = 69632;
constexpr int SMEM_GEMM = 102400;         // hs[128][68] (34816) unioned at 0

__global__ __launch_bounds__(512) void gemm_mma(const float* __restrict__ A,
                                                const float* __restrict__ a_src,
                                                const float* __restrict__ a_dst) {
    extern __shared__ char gsm[];
    const u32 sbase = smem_u32(gsm);

    const int tid = threadIdx.x;
    const int w = tid >> 5, lane = tid & 31;
    const int bm = blockIdx.x;
    const int rg = w >> 2, cg = w & 3;
    const int grp = lane >> 2;
    const int tig = lane & 3;
    const int r0 = rg * 16;

    const u32 x_off[2]  = { sbase + GOFF_X0,  sbase + GOFF_X1 };
    const u32 wf_off[2] = { sbase + GOFF_WF0, sbase + GOFF_WF1 };

    auto stage = [&](int s, int sel) {
#pragma unroll
        for (int q = 0; q < 2; ++q) {
            int v = (q << 9) + tid;
            int row = v >> 3, c4 = (v & 7) << 2;
            cpasync16(x_off[sel] + (u32)(row * XROW + c4) * 4u,
                      A + (size_t)(bm * 128 + row) * Dd + (s << 5) + c4);
        }
#pragma unroll
        for (int q = 0; q < 4; ++q) {
            int v = (q << 9) + tid;
            int bn = v >> 9;
            int rest = v & 511;
            const uint4* src = (const uint4*)(g_wf + (size_t)((bn * 32 + (s << 2)) * 8) * 32) + rest;
            cpasync16(wf_off[sel] + (u32)((bn * 512 + rest)) * 16u, src);
        }
    };

    float acc0[8][4], acc1[8][4];
#pragma unroll
    for (int n = 0; n < 8; ++n)
#pragma unroll
        for (int k = 0; k < 4; ++k) { acc0[n][k] = 0.f; acc1[n][k] = 0.f; }

    stage(0, 0); CP_COMMIT();

    for (int s = 0; s < 8; ++s) {
        const int sel = s & 1;
        if (s < 7) { stage(s + 1, sel ^ 1); CP_COMMIT(); }
        if (s < 7) CP_WAIT1(); else CP_WAIT0();
        __syncthreads();

        const float* xs = (const float*)(gsm + (sel ? GOFF_X1 : GOFF_X0));
        const uint2* wfs = (const uint2*)(gsm + (sel ? GOFF_WF1 : GOFF_WF0));

#pragma unroll
        for (int k8 = 0; k8 < 4; ++k8) {
            const int kc = (k8 << 3) + tig;
            u32 a0 = rnd_tf32(xs[(r0 + grp) * XROW + kc]);
            u32 a1 = rnd_tf32(xs[(r0 + 8 + grp) * XROW + kc]);
            u32 a2 = rnd_tf32(xs[(r0 + grp) * XROW + kc + 4]);
            u32 a3 = rnd_tf32(xs[(r0 + 8 + grp) * XROW + kc + 4]);
            u32 a4 = rnd_tf32(xs[(64 + r0 + grp) * XROW + kc]);
            u32 a5 = rnd_tf32(xs[(64 + r0 + 8 + grp) * XROW + kc]);
            u32 a6 = rnd_tf32(xs[(64 + r0 + grp) * XROW + kc + 4]);
            u32 a7 = rnd_tf32(xs[(64 + r0 + 8 + grp) * XROW + kc + 4]);
            const uint2* wr = wfs + ((cg * 4 + k8) << 8) + lane;
#pragma unroll
            for (int n = 0; n < 8; ++n) {
                uint2 bf = wr[n << 5];
                mma16n8k8(acc0[n], a0, a1, a2, a3, bf.x, bf.y);
                mma16n8k8(acc1[n], a4, a5, a6, a7, bf.x, bf.y);
            }
        }
        __syncthreads();
    }

    // ---- e_src/e_dst: warp-local ----
    {
        float ps0 = 0.f, ps1 = 0.f, pd0 = 0.f, pd1 = 0.f;
        float qs0 = 0.f, qs1 = 0.f, qd0 = 0.f, qd1 = 0.f;
#pragma unroll
        for (int n = 0; n < 8; ++n) {
            float2 asv = *(const float2*)&a_src[cg * 64 + (n << 3) + (tig << 1)];
            float2 adv = *(const float2*)&a_dst[cg * 64 + (n << 3) + (tig << 1)];
            ps0 = fmaf(acc0[n][0], asv.x, fmaf(acc0[n][1], asv.y, ps0));
            ps1 = fmaf(acc0[n][2], asv.x, fmaf(acc0[n][3], asv.y, ps1));
            pd0 = fmaf(acc0[n][0], adv.x, fmaf(acc0[n][1], adv.y, pd0));
            pd1 = fmaf(acc0[n][2], adv.x, fmaf(acc0[n][3], adv.y, pd1));
            qs0 = fmaf(acc1[n][0], asv.x, fmaf(acc1[n][1], asv.y, qs0));
            qs1 = fmaf(acc1[n][2], asv.x, fmaf(acc1[n][3], asv.y, qs1));
            qd0 = fmaf(acc1[n][0], adv.x, fmaf(acc1[n][1], adv.y, qd0));
            qd1 = fmaf(acc1[n][2], adv.x, fmaf(acc1[n][3], adv.y, qd1));
        }
#pragma unroll
        for (int o = 1; o < 4; o <<= 1) {
            ps0 += __shfl_xor_sync(0xffffffffu, ps0, o);
            ps1 += __shfl_xor_sync(0xffffffffu, ps1, o);
            pd0 += __shfl_xor_sync(0xffffffffu, pd0, o);
            pd1 += __shfl_xor_sync(0xffffffffu, pd1, o);
            qs0 += __shfl_xor_sync(0xffffffffu, qs0, o);
            qs1 += __shfl_xor_sync(0xffffffffu, qs1, o);
            qd0 += __shfl_xor_sync(0xffffffffu, qd0, o);
            qd1 += __shfl_xor_sync(0xffffffffu, qd1, o);
        }
        if (tig == 0) {
            const int base = cg * Mrows + bm * 128;
            g_es[base + r0 + grp]           = ps0 * LOG2E;
            g_es[base + r0 + 8 + grp]       = ps1 * LOG2E;
            g_ed[base + r0 + grp]           = pd0 * LOG2E;
            g_ed[base + r0 + 8 + grp]       = pd1 * LOG2E;
            g_es[base + 64 + r0 + grp]      = qs0 * LOG2E;
            g_es[base + 64 + r0 + 8 + grp]  = qs1 * LOG2E;
            g_ed[base + 64 + r0 + grp]      = qd0 * LOG2E;
            g_ed[base + 64 + r0 + 8 + grp]  = qd1 * LOG2E;
        }
    }

    // ---- per-head hs bounce + fp16 fragment emission ----
    float (*hs)[68] = (float(*)[68])gsm;
    const int b_ = bm >> 3;

    for (int hh = 0; hh < 4; ++hh) {
        __syncthreads();
        if (cg == hh) {
#pragma unroll
            for (int n = 0; n < 8; ++n) {
                const int col = (n << 3) + (tig << 1);
                hs[r0 + grp][col]          = acc0[n][0];
                hs[r0 + grp][col + 1]      = acc0[n][1];
                hs[r0 + 8 + grp][col]      = acc0[n][2];
                hs[r0 + 8 + grp][col + 1]  = acc0[n][3];
                hs[64 + r0 + grp][col]         = acc1[n][0];
                hs[64 + r0 + grp][col + 1]     = acc1[n][1];
                hs[64 + r0 + 8 + grp][col]     = acc1[n][2];
                hs[64 + r0 + 8 + grp][col + 1] = acc1[n][3];
            }
        }
        __syncthreads();

        const int bh = b_ * 4 + hh;
#pragma unroll
        for (int q2 = 0; q2 < 4; ++q2) {
            int v = (q2 << 9) + tid;       // 0..2047
            int jbl = v >> 8;              // 0..7 (local k16 block)
            int nf = (v >> 5) & 7;
            int ln = v & 31;
            int jl = (jbl << 4) + ((ln & 3) << 1);
            int f = (nf << 3) + (ln >> 2);
            uint2 o;
            o.x = packhf(hs[jl][f],     hs[jl + 1][f]);
            o.y = packhf(hs[jl + 8][f], hs[jl + 9][f]);
            g_hBf[(size_t)(((bh * 64 + (bm & 7) * 8 + jbl) * 8 + nf)) * 32 + ln] = o;
        }
    }
}

// ---------------------------------------------------------------------------
// Kernel 2: flash-GAT attention, fp16 m16n8k16 aggregation.
// Grid (8 i-tiles, 64 bh), 256 thr.
// ---------------------------------------------------------------------------
constexpr int ADJ_ST = 68;
constexpr int OFF_ADJ0 = 0;                    // 34816
constexpr int OFF_ADJ1 = 34816;
constexpr int OFF_HF0  = 69632;                // 8192
constexpr int OFF_HF1  = 77824;
constexpr int OFF_ES0  = 86016;                // 256
constexpr int OFF_ES1  = 86272;
constexpr int OFF_ED   = 86528;                // 512
constexpr int OFF_DEN  = 87040;                // 512
constexpr int SMEM_ATTN = 87552;

__global__ __launch_bounds__(256, 2) void attn_kernel(const float* __restrict__ adj,
                                                      const float* __restrict__ bias,
                                                      float* __restrict__ out) {
    extern __shared__ char dsm[];
    const u32 sbase = smem_u32(dsm);
    float* ed_sm  = (float*)(dsm + OFF_ED);
    float* den_sm = (float*)(dsm + OFF_DEN);

    const int tid = threadIdx.x;
    const int w = tid >> 5, lane = tid & 31;
    const int bh = blockIdx.y, b = bh >> 2, h = bh & 3;
    const int i0 = blockIdx.x << 7;
    const int i_w = w << 4;
    const int grp = lane >> 2;
    const int tig = lane & 3;

    const u32 adj_off[2] = { sbase + OFF_ADJ0, sbase + OFF_ADJ1 };
    const u32 hf_off[2]  = { sbase + OFF_HF0,  sbase + OFF_HF1 };
    const u32 es_off[2]  = { sbase + OFF_ES0,  sbase + OFF_ES1 };

    const float* adj_base = adj + (size_t)(b * Nn + i0) * Nn;
    const uint2* hf_base = g_hBf + (size_t)bh * 64 * 8 * 32;
    const float* es_base = g_es + h * Mrows + b * Nn;

    auto stage = [&](int jt, int sel) {
        const int j0 = jt << 6;
        const int r = tid >> 4, c4 = (tid & 15) << 2;
#pragma unroll
        for (int q = 0; q < 8; ++q)
            cpasync16(adj_off[sel] + (u32)(((q << 4) + r) * ADJ_ST + c4) * 4u,
                      adj_base + (size_t)((q << 4) + r) * Nn + j0 + c4);
        // fragments: 4 k16-blocks x 8 nf x 32 lanes = 512 uint4 (8KB)
        const uint4* hsrc = (const uint4*)(hf_base + (size_t)(jt * 4) * 8 * 32);
#pragma unroll
        for (int q = 0; q < 2; ++q)
            cpasync16(hf_off[sel] + (u32)((q << 8) + tid) * 16u, hsrc + (q << 8) + tid);
        if (tid < 16)
            cpasync16(es_off[sel] + (u32)tid * 16u, es_base + j0 + tid * 4);
    };

    stage(0, 0); CP_COMMIT();
    if (tid < 128) ed_sm[tid] = g_ed[h * Mrows + b * Nn + i0 + tid];

    float acc[8][4];
#pragma unroll
    for (int n = 0; n < 8; ++n)
#pragma unroll
        for (int k = 0; k < 4; ++k) acc[n][k] = 0.f;
    float den0 = 0.f, den1 = 0.f;

    __syncthreads();
    const float ed0 = ed_sm[i_w + grp];
    const float ed1 = ed_sm[i_w + 8 + grp];

    for (int jt = 0; jt < 16; ++jt) {
        const int sel = jt & 1;
        if (jt < 15) { stage(jt + 1, sel ^ 1); CP_COMMIT(); }
        if (jt < 15) CP_WAIT1(); else CP_WAIT0();
        __syncthreads();

        const float* adj_sm = (const float*)(dsm + (sel ? OFF_ADJ1 : OFF_ADJ0));
        const uint2* hfrag  = (const uint2*)(dsm + (sel ? OFF_HF1 : OFF_HF0));
        const float* es_sm  = (const float*)(dsm + (sel ? OFF_ES1 : OFF_ES0));

#pragma unroll
        for (int ks = 0; ks < 4; ++ks) {
            const int jj = (ks << 4) + (tig << 1);     // k16 block, this lane's j pair
            float2 esA = *(const float2*)&es_sm[jj];       // j, j+1
            float2 esB = *(const float2*)&es_sm[jj + 8];   // j+8, j+9
            float2 aj0 = *(const float2*)&adj_sm[(i_w + grp) * ADJ_ST + jj];
            float2 aj1 = *(const float2*)&adj_sm[(i_w + 8 + grp) * ADJ_ST + jj];
            float2 aj2 = *(const float2*)&adj_sm[(i_w + grp) * ADJ_ST + jj + 8];
            float2 aj3 = *(const float2*)&adj_sm[(i_w + 8 + grp) * ADJ_ST + jj + 8];

            float l00 = ed0 + esA.x; l00 = fmaxf(l00, 0.2f * l00);
            float l01 = ed0 + esA.y; l01 = fmaxf(l01, 0.2f * l01);
            float l02 = ed0 + esB.x; l02 = fmaxf(l02, 0.2f * l02);
            float l03 = ed0 + esB.y; l03 = fmaxf(l03, 0.2f * l03);
            float l10 = ed1 + esA.x; l10 = fmaxf(l10, 0.2f * l10);
            float l11 = ed1 + esA.y; l11 = fmaxf(l11, 0.2f * l11);
            float l12 = ed1 + esB.x; l12 = fmaxf(l12, 0.2f * l12);
            float l13 = ed1 + esB.y; l13 = fmaxf(l13, 0.2f * l13);

            float p00 = (aj0.x > 0.5f) ? ex2f(l00) : 0.f;
            float p01 = (aj0.y > 0.5f) ? ex2f(l01) : 0.f;
            float p02 = (aj2.x > 0.5f) ? ex2f(l02) : 0.f;
            float p03 = (aj2.y > 0.5f) ? ex2f(l03) : 0.f;
            float p10 = (aj1.x > 0.5f) ? ex2f(l10) : 0.f;
            float p11 = (aj1.y > 0.5f) ? ex2f(l11) : 0.f;
            float p12 = (aj3.x > 0.5f) ? ex2f(l12) : 0.f;
            float p13 = (aj3.y > 0.5f) ? ex2f(l13) : 0.f;

            const u32 a0 = packhf(p00, p01);   // row grp,  k pair (j, j+1)
            const u32 a1 = packhf(p10, p11);   // row grp+8
            const u32 a2 = packhf(p02, p03);   // row grp,  k pair (j+8, j+9)
            const u32 a3 = packhf(p12, p13);   // row grp+8

            den0 += (p00 + p01) + (p02 + p03);
            den1 += (p10 + p11) + (p12 + p13);

            const uint2* hrow = hfrag + (ks << 8) + lane;   // (ks*8+nf)*32+lane
#pragma unroll
            for (int n = 0; n < 8; ++n) {
                uint2 bf = hrow[n << 5];
                mma16n8k16hf(acc[n], a0, a1, a2, a3, bf.x, bf.y);
            }
        }
        __syncthreads();
    }

    den0 += __shfl_xor_sync(0xffffffffu, den0, 1);
    den0 += __shfl_xor_sync(0xffffffffu, den0, 2);
    den1 += __shfl_xor_sync(0xffffffffu, den1, 1);
    den1 += __shfl_xor_sync(0xffffffffu, den1, 2);
    if (tig == 0) {
        den_sm[i_w + grp] = den0;
        den_sm[i_w + 8 + grp] = den1;
    }
    __syncthreads();
    const float inv0 = 1.0f / den_sm[i_w + grp];
    const float inv1 = 1.0f / den_sm[i_w + 8 + grp];

    float* o0 = out + (size_t)(b * Nn + i0 + i_w + grp) * HF + h * 64;
    float* o1 = out + (size_t)(b * Nn + i0 + i_w + 8 + grp) * HF + h * 64;
#pragma unroll
    for (int n = 0; n < 8; ++n) {
        const int col = (n << 3) + (tig << 1);
        float2 bz = *(const float2*)&bias[h * 64 + col];
        float2 r0, r1;
        r0.x = acc[n][0] * inv0 + bz.x;  r0.y = acc[n][1] * inv0 + bz.y;
        r1.x = acc[n][2] * inv1 + bz.x;  r1.y = acc[n][3] * inv1 + bz.y;
        *(float2*)&o0[col] = r0;
        *(float2*)&o1[col] = r1;
    }
}

// ---------------------------------------------------------------------------
extern "C" void kernel_launch(void* const* d_in, const int* in_sizes, int n_in,
                              void* d_out, int out_size) {
    (void)in_sizes; (void)n_in; (void)out_size;
    const float* x     = (const float*)d_in[0];
    const float* adj   = (const float*)d_in[1];
    const float* W     = (const float*)d_in[2];
    const float* a_src = (const float*)d_in[3];
    const float* a_dst = (const float*)d_in[4];
    const float* bias  = (const float*)d_in[5];
    float* out = (float*)d_out;

    cudaFuncSetAttribute(gemm_mma,
                         cudaFuncAttributeMaxDynamicSharedMemorySize, SMEM_GEMM);
    cudaFuncSetAttribute(attn_kernel,
                         cudaFuncAttributeMaxDynamicSharedMemorySize, SMEM_ATTN);

    wfrag_kernel<<<32, 256>>>(W);
    gemm_mma<<<128, 512, SMEM_GEMM>>>(x, a_src, a_dst);
    attn_kernel<<<dim3(8, 64), 256, SMEM_ATTN>>>(adj, bias, out);
}

// round 15
// speedup vs baseline: 3.0291x; 1.0608x over previous
#include <cuda_runtime.h>
#include <cstdint>

// BatchedGAT round 14:
//   wfrag_kernel: W -> fp16 m16n8k16 B-fragments (128KB, grid 64).
//   gemm_mma: h = x@W on fp16 m16n8k16 (tf32 k8 replaced: same 10-bit
//             mantissa, half the MMAs and half the W bytes). fp32 accum.
//             Epilogue (e_src/e_dst + fp16 attn-fragment emission) unchanged.
//   attn: unchanged fp16 m16n8k16 flash-GAT (R13, proven 3.17e-4).

#define DEV __device__ __forceinline__
using u64 = unsigned long long;
using u32 = unsigned int;

DEV float ex2f(float x) {
    float r; asm("ex2.approx.f32 %0, %1;" : "=f"(r) : "f"(x)); return r;
}
// pack {lo, hi} floats -> f16x2 (lo in low half)
DEV u32 packhf(float lo, float hi) {
    u32 r; asm("cvt.rn.f16x2.f32 %0, %1, %2;" : "=r"(r) : "f"(hi), "f"(lo));
    return r;
}
DEV u32 smem_u32(const void* p) {
    u32 a; asm("{ .reg .u64 t; cvta.to.shared.u64 t, %1; cvt.u32.u64 %0, t; }"
               : "=r"(a) : "l"(p));
    return a;
}
DEV void cpasync16(u32 dst, const void* src) {
    asm volatile("cp.async.cg.shared.global [%0], [%1], 16;"
                 :: "r"(dst), "l"(src) : "memory");
}
#define CP_COMMIT() asm volatile("cp.async.commit_group;" ::: "memory")
#define CP_WAIT1()  asm volatile("cp.async.wait_group 1;" ::: "memory")
#define CP_WAIT0()  asm volatile("cp.async.wait_group 0;" ::: "memory")

DEV void mma16n8k16hf(float* c, u32 a0, u32 a1, u32 a2, u32 a3, u32 b0, u32 b1) {
    asm volatile(
        "mma.sync.aligned.m16n8k16.row.col.f32.f16.f16.f32 "
        "{%0,%1,%2,%3}, {%4,%5,%6,%7}, {%8,%9}, {%0,%1,%2,%3};"
        : "+f"(c[0]), "+f"(c[1]), "+f"(c[2]), "+f"(c[3])
        : "r"(a0), "r"(a1), "r"(a2), "r"(a3), "r"(b0), "r"(b1));
}

constexpr int Bb = 16, Nn = 1024, Dd = 256, Hh = 4, HF = 256;
constexpr int Mrows = Bb * Nn;
constexpr float LOG2E = 1.4426950408889634f;

// e arrays transposed [h][b*N+n], PRE-SCALED by log2e.
__device__ float g_es[Hh * Mrows];
__device__ float g_ed[Hh * Mrows];
// attn B fragments (fp16 m16n8k16): [bh][jb16(64)][nf(8)][lane(32)] uint2
__device__ uint2 g_hBf[64 * 64 * 8 * 32];     // 8.4 MB
// W fragments (fp16 m16n8k16): [bn(4)][k16(16)][nf(8)][lane(32)] uint2
__device__ uint2 g_wf16[4 * 16 * 8 * 32];     // 128 KB

// ---------------------------------------------------------------------------
// Kernel 0: W -> fp16 m16n8k16 B-fragment layout (col-major).
// frag(bn,k16,nf)[lane]: tig=lane&3, grp=lane>>2, col=bn*64+nf*8+grp,
//   o.x = {W[k16*16+2tig][col], W[+1][col]}, o.y = {W[k16*16+8+2tig], [+1]}.
// ---------------------------------------------------------------------------
__global__ __launch_bounds__(256) void wfrag_kernel(const float* __restrict__ W) {
    const int v = blockIdx.x * 256 + threadIdx.x;   // 0..16383
    const int bn = v >> 12;
    const int k16 = (v >> 8) & 15;
    const int nf = (v >> 5) & 7;
    const int ln = v & 31;
    const int k = (k16 << 4) + ((ln & 3) << 1);
    const int col = bn * 64 + (nf << 3) + (ln >> 2);
    uint2 o;
    o.x = packhf(__ldg(&W[k * HF + col]),       __ldg(&W[(k + 1) * HF + col]));
    o.y = packhf(__ldg(&W[(k + 8) * HF + col]), __ldg(&W[(k + 9) * HF + col]));
    g_wf16[((bn * 16 + k16) * 8 + nf) * 32 + ln] = o;
}

// ---------------------------------------------------------------------------
// Kernel 1: gemm via mma.sync fp16 k16 + fused e + fp16 attn-frag emission.
// Grid 128 (bm), 512 thr, 16 warps. Warp w: rg=w>>2 (rows), cg=w&3 (head).
// K pipelined in 8 slabs of 32 (2 k16 blocks each), cp.async double buffer.
// ---------------------------------------------------------------------------
constexpr int XROW = 36;
constexpr int GOFF_X0  = 0;               // 18432
constexpr int GOFF_X1  = 18432;
constexpr int GOFF_WF0 = 36864;           // 16384 (4 heads x 2 k16 blocks)
constexpr int GOFF_WF1 = 53248;
constexpr int SMEM_GEMM = 69632;          // hs[128][68] (34816) unioned at 0

__global__ __launch_bounds__(512) void gemm_mma(const float* __restrict__ A,
                                                const float* __restrict__ a_src,
                                                const float* __restrict__ a_dst) {
    extern __shared__ char gsm[];
    const u32 sbase = smem_u32(gsm);

    const int tid = threadIdx.x;
    const int w = tid >> 5, lane = tid & 31;
    const int bm = blockIdx.x;
    const int rg = w >> 2, cg = w & 3;
    const int grp = lane >> 2;
    const int tig = lane & 3;
    const int r0 = rg * 16;

    const u32 x_off[2]  = { sbase + GOFF_X0,  sbase + GOFF_X1 };
    const u32 wf_off[2] = { sbase + GOFF_WF0, sbase + GOFF_WF1 };

    auto stage = [&](int s, int sel) {
        // x slab: 128 rows x 32 floats -> 1024 float4, 2 per thread
#pragma unroll
        for (int q = 0; q < 2; ++q) {
            int v = (q << 9) + tid;
            int row = v >> 3, c4 = (v & 7) << 2;
            cpasync16(x_off[sel] + (u32)(row * XROW + c4) * 4u,
                      A + (size_t)(bm * 128 + row) * Dd + (s << 5) + c4);
        }
        // W frags: 4 heads x 2 k16 blocks x 8 nf x 32 ln uint2 = 16KB = 1024 uint4
#pragma unroll
        for (int q = 0; q < 2; ++q) {
            int v = (q << 9) + tid;       // 0..1023
            int bn = v >> 8;
            int rest = v & 255;
            const uint4* src = (const uint4*)(g_wf16 + (size_t)((bn * 16 + (s << 1)) * 8) * 32) + rest;
            cpasync16(wf_off[sel] + (u32)(bn * 256 + rest) * 16u, src);
        }
    };

    float acc0[8][4], acc1[8][4];
#pragma unroll
    for (int n = 0; n < 8; ++n)
#pragma unroll
        for (int k = 0; k < 4; ++k) { acc0[n][k] = 0.f; acc1[n][k] = 0.f; }

    stage(0, 0); CP_COMMIT();

    for (int s = 0; s < 8; ++s) {
        const int sel = s & 1;
        if (s < 7) { stage(s + 1, sel ^ 1); CP_COMMIT(); }
        if (s < 7) CP_WAIT1(); else CP_WAIT0();
        __syncthreads();

        const float* xs = (const float*)(gsm + (sel ? GOFF_X1 : GOFF_X0));
        const uint2* wfs = (const uint2*)(gsm + (sel ? GOFF_WF1 : GOFF_WF0));

#pragma unroll
        for (int kb = 0; kb < 2; ++kb) {
            const int kc = (kb << 4) + (tig << 1);
            float2 v0a = *(const float2*)&xs[(r0 + grp) * XROW + kc];
            float2 v0b = *(const float2*)&xs[(r0 + grp) * XROW + kc + 8];
            float2 v1a = *(const float2*)&xs[(r0 + 8 + grp) * XROW + kc];
            float2 v1b = *(const float2*)&xs[(r0 + 8 + grp) * XROW + kc + 8];
            float2 v2a = *(const float2*)&xs[(64 + r0 + grp) * XROW + kc];
            float2 v2b = *(const float2*)&xs[(64 + r0 + grp) * XROW + kc + 8];
            float2 v3a = *(const float2*)&xs[(64 + r0 + 8 + grp) * XROW + kc];
            float2 v3b = *(const float2*)&xs[(64 + r0 + 8 + grp) * XROW + kc + 8];
            u32 a0 = packhf(v0a.x, v0a.y);
            u32 a1 = packhf(v1a.x, v1a.y);
            u32 a2 = packhf(v0b.x, v0b.y);
            u32 a3 = packhf(v1b.x, v1b.y);
            u32 a4 = packhf(v2a.x, v2a.y);
            u32 a5 = packhf(v3a.x, v3a.y);
            u32 a6 = packhf(v2b.x, v2b.y);
            u32 a7 = packhf(v3b.x, v3b.y);
            const uint2* wr = wfs + (((cg << 1) + kb) << 8) + lane;
#pragma unroll
            for (int n = 0; n < 8; ++n) {
                uint2 bf = wr[n << 5];
                mma16n8k16hf(acc0[n], a0, a1, a2, a3, bf.x, bf.y);
                mma16n8k16hf(acc1[n], a4, a5, a6, a7, bf.x, bf.y);
            }
        }
        __syncthreads();
    }

    // ---- e_src/e_dst: warp-local ----
    {
        float ps0 = 0.f, ps1 = 0.f, pd0 = 0.f, pd1 = 0.f;
        float qs0 = 0.f, qs1 = 0.f, qd0 = 0.f, qd1 = 0.f;
#pragma unroll
        for (int n = 0; n < 8; ++n) {
            float2 asv = *(const float2*)&a_src[cg * 64 + (n << 3) + (tig << 1)];
            float2 adv = *(const float2*)&a_dst[cg * 64 + (n << 3) + (tig << 1)];
            ps0 = fmaf(acc0[n][0], asv.x, fmaf(acc0[n][1], asv.y, ps0));
            ps1 = fmaf(acc0[n][2], asv.x, fmaf(acc0[n][3], asv.y, ps1));
            pd0 = fmaf(acc0[n][0], adv.x, fmaf(acc0[n][1], adv.y, pd0));
            pd1 = fmaf(acc0[n][2], adv.x, fmaf(acc0[n][3], adv.y, pd1));
            qs0 = fmaf(acc1[n][0], asv.x, fmaf(acc1[n][1], asv.y, qs0));
            qs1 = fmaf(acc1[n][2], asv.x, fmaf(acc1[n][3], asv.y, qs1));
            qd0 = fmaf(acc1[n][0], adv.x, fmaf(acc1[n][1], adv.y, qd0));
            qd1 = fmaf(acc1[n][2], adv.x, fmaf(acc1[n][3], adv.y, qd1));
        }
#pragma unroll
        for (int o = 1; o < 4; o <<= 1) {
            ps0 += __shfl_xor_sync(0xffffffffu, ps0, o);
            ps1 += __shfl_xor_sync(0xffffffffu, ps1, o);
            pd0 += __shfl_xor_sync(0xffffffffu, pd0, o);
            pd1 += __shfl_xor_sync(0xffffffffu, pd1, o);
            qs0 += __shfl_xor_sync(0xffffffffu, qs0, o);
            qs1 += __shfl_xor_sync(0xffffffffu, qs1, o);
            qd0 += __shfl_xor_sync(0xffffffffu, qd0, o);
            qd1 += __shfl_xor_sync(0xffffffffu, qd1, o);
        }
        if (tig == 0) {
            const int base = cg * Mrows + bm * 128;
            g_es[base + r0 + grp]           = ps0 * LOG2E;
            g_es[base + r0 + 8 + grp]       = ps1 * LOG2E;
            g_ed[base + r0 + grp]           = pd0 * LOG2E;
            g_ed[base + r0 + 8 + grp]       = pd1 * LOG2E;
            g_es[base + 64 + r0 + grp]      = qs0 * LOG2E;
            g_es[base + 64 + r0 + 8 + grp]  = qs1 * LOG2E;
            g_ed[base + 64 + r0 + grp]      = qd0 * LOG2E;
            g_ed[base + 64 + r0 + 8 + grp]  = qd1 * LOG2E;
        }
    }

    // ---- per-head hs bounce + fp16 fragment emission ----
    float (*hs)[68] = (float(*)[68])gsm;
    const int b_ = bm >> 3;

    for (int hh = 0; hh < 4; ++hh) {
        __syncthreads();
        if (cg == hh) {
#pragma unroll
            for (int n = 0; n < 8; ++n) {
                const int col = (n << 3) + (tig << 1);
                hs[r0 + grp][col]          = acc0[n][0];
                hs[r0 + grp][col + 1]      = acc0[n][1];
                hs[r0 + 8 + grp][col]      = acc0[n][2];
                hs[r0 + 8 + grp][col + 1]  = acc0[n][3];
                hs[64 + r0 + grp][col]         = acc1[n][0];
                hs[64 + r0 + grp][col + 1]     = acc1[n][1];
                hs[64 + r0 + 8 + grp][col]     = acc1[n][2];
                hs[64 + r0 + 8 + grp][col + 1] = acc1[n][3];
            }
        }
        __syncthreads();

        const int bh = b_ * 4 + hh;
#pragma unroll
        for (int q2 = 0; q2 < 4; ++q2) {
            int v = (q2 << 9) + tid;       // 0..2047
            int jbl = v >> 8;              // 0..7 (local k16 block)
            int nf = (v >> 5) & 7;
            int ln = v & 31;
            int jl = (jbl << 4) + ((ln & 3) << 1);
            int f = (nf << 3) + (ln >> 2);
            uint2 o;
            o.x = packhf(hs[jl][f],     hs[jl + 1][f]);
            o.y = packhf(hs[jl + 8][f], hs[jl + 9][f]);
            g_hBf[(size_t)(((bh * 64 + (bm & 7) * 8 + jbl) * 8 + nf)) * 32 + ln] = o;
        }
    }
}

// ---------------------------------------------------------------------------
// Kernel 2: flash-GAT attention, fp16 m16n8k16 aggregation (unchanged).
// ---------------------------------------------------------------------------
constexpr int ADJ_ST = 68;
constexpr int OFF_ADJ0 = 0;                    // 34816
constexpr int OFF_ADJ1 = 34816;
constexpr int OFF_HF0  = 69632;                // 8192
constexpr int OFF_HF1  = 77824;
constexpr int OFF_ES0  = 86016;                // 256
constexpr int OFF_ES1  = 86272;
constexpr int OFF_ED   = 86528;                // 512
constexpr int OFF_DEN  = 87040;                // 512
constexpr int SMEM_ATTN = 87552;

__global__ __launch_bounds__(256, 2) void attn_kernel(const float* __restrict__ adj,
                                                      const float* __restrict__ bias,
                                                      float* __restrict__ out) {
    extern __shared__ char dsm[];
    const u32 sbase = smem_u32(dsm);
    float* ed_sm  = (float*)(dsm + OFF_ED);
    float* den_sm = (float*)(dsm + OFF_DEN);

    const int tid = threadIdx.x;
    const int w = tid >> 5, lane = tid & 31;
    const int bh = blockIdx.y, b = bh >> 2, h = bh & 3;
    const int i0 = blockIdx.x << 7;
    const int i_w = w << 4;
    const int grp = lane >> 2;
    const int tig = lane & 3;

    const u32 adj_off[2] = { sbase + OFF_ADJ0, sbase + OFF_ADJ1 };
    const u32 hf_off[2]  = { sbase + OFF_HF0,  sbase + OFF_HF1 };
    const u32 es_off[2]  = { sbase + OFF_ES0,  sbase + OFF_ES1 };

    const float* adj_base = adj + (size_t)(b * Nn + i0) * Nn;
    const uint2* hf_base = g_hBf + (size_t)bh * 64 * 8 * 32;
    const float* es_base = g_es + h * Mrows + b * Nn;

    auto stage = [&](int jt, int sel) {
        const int j0 = jt << 6;
        const int r = tid >> 4, c4 = (tid & 15) << 2;
#pragma unroll
        for (int q = 0; q < 8; ++q)
            cpasync16(adj_off[sel] + (u32)(((q << 4) + r) * ADJ_ST + c4) * 4u,
                      adj_base + (size_t)((q << 4) + r) * Nn + j0 + c4);
        const uint4* hsrc = (const uint4*)(hf_base + (size_t)(jt * 4) * 8 * 32);
#pragma unroll
        for (int q = 0; q < 2; ++q)
            cpasync16(hf_off[sel] + (u32)((q << 8) + tid) * 16u, hsrc + (q << 8) + tid);
        if (tid < 16)
            cpasync16(es_off[sel] + (u32)tid * 16u, es_base + j0 + tid * 4);
    };

    stage(0, 0); CP_COMMIT();
    if (tid < 128) ed_sm[tid] = g_ed[h * Mrows + b * Nn + i0 + tid];

    float acc[8][4];
#pragma unroll
    for (int n = 0; n < 8; ++n)
#pragma unroll
        for (int k = 0; k < 4; ++k) acc[n][k] = 0.f;
    float den0 = 0.f, den1 = 0.f;

    __syncthreads();
    const float ed0 = ed_sm[i_w + grp];
    const float ed1 = ed_sm[i_w + 8 + grp];

    for (int jt = 0; jt < 16; ++jt) {
        const int sel = jt & 1;
        if (jt < 15) { stage(jt + 1, sel ^ 1); CP_COMMIT(); }
        if (jt < 15) CP_WAIT1(); else CP_WAIT0();
        __syncthreads();

        const float* adj_sm = (const float*)(dsm + (sel ? OFF_ADJ1 : OFF_ADJ0));
        const uint2* hfrag  = (const uint2*)(dsm + (sel ? OFF_HF1 : OFF_HF0));
        const float* es_sm  = (const float*)(dsm + (sel ? OFF_ES1 : OFF_ES0));

#pragma unroll
        for (int ks = 0; ks < 4; ++ks) {
            const int jj = (ks << 4) + (tig << 1);
            float2 esA = *(const float2*)&es_sm[jj];
            float2 esB = *(const float2*)&es_sm[jj + 8];
            float2 aj0 = *(const float2*)&adj_sm[(i_w + grp) * ADJ_ST + jj];
            float2 aj1 = *(const float2*)&adj_sm[(i_w + 8 + grp) * ADJ_ST + jj];
            float2 aj2 = *(const float2*)&adj_sm[(i_w + grp) * ADJ_ST + jj + 8];
            float2 aj3 = *(const float2*)&adj_sm[(i_w + 8 + grp) * ADJ_ST + jj + 8];

            float l00 = ed0 + esA.x; l00 = fmaxf(l00, 0.2f * l00);
            float l01 = ed0 + esA.y; l01 = fmaxf(l01, 0.2f * l01);
            float l02 = ed0 + esB.x; l02 = fmaxf(l02, 0.2f * l02);
            float l03 = ed0 + esB.y; l03 = fmaxf(l03, 0.2f * l03);
            float l10 = ed1 + esA.x; l10 = fmaxf(l10, 0.2f * l10);
            float l11 = ed1 + esA.y; l11 = fmaxf(l11, 0.2f * l11);
            float l12 = ed1 + esB.x; l12 = fmaxf(l12, 0.2f * l12);
            float l13 = ed1 + esB.y; l13 = fmaxf(l13, 0.2f * l13);

            float p00 = (aj0.x > 0.5f) ? ex2f(l00) : 0.f;
            float p01 = (aj0.y > 0.5f) ? ex2f(l01) : 0.f;
            float p02 = (aj2.x > 0.5f) ? ex2f(l02) : 0.f;
            float p03 = (aj2.y > 0.5f) ? ex2f(l03) : 0.f;
            float p10 = (aj1.x > 0.5f) ? ex2f(l10) : 0.f;
            float p11 = (aj1.y > 0.5f) ? ex2f(l11) : 0.f;
            float p12 = (aj3.x > 0.5f) ? ex2f(l12) : 0.f;
            float p13 = (aj3.y > 0.5f) ? ex2f(l13) : 0.f;

            const u32 a0 = packhf(p00, p01);
            const u32 a1 = packhf(p10, p11);
            const u32 a2 = packhf(p02, p03);
            const u32 a3 = packhf(p12, p13);

            den0 += (p00 + p01) + (p02 + p03);
            den1 += (p10 + p11) + (p12 + p13);

            const uint2* hrow = hfrag + (ks << 8) + lane;
#pragma unroll
            for (int n = 0; n < 8; ++n) {
                uint2 bf = hrow[n << 5];
                mma16n8k16hf(acc[n], a0, a1, a2, a3, bf.x, bf.y);
            }
        }
        __syncthreads();
    }

    den0 += __shfl_xor_sync(0xffffffffu, den0, 1);
    den0 += __shfl_xor_sync(0xffffffffu, den0, 2);
    den1 += __shfl_xor_sync(0xffffffffu, den1, 1);
    den1 += __shfl_xor_sync(0xffffffffu, den1, 2);
    if (tig == 0) {
        den_sm[i_w + grp] = den0;
        den_sm[i_w + 8 + grp] = den1;
    }
    __syncthreads();
    const float inv0 = 1.0f / den_sm[i_w + grp];
    const float inv1 = 1.0f / den_sm[i_w + 8 + grp];

    float* o0 = out + (size_t)(b * Nn + i0 + i_w + grp) * HF + h * 64;
    float* o1 = out + (size_t)(b * Nn + i0 + i_w + 8 + grp) * HF + h * 64;
#pragma unroll
    for (int n = 0; n < 8; ++n) {
        const int col = (n << 3) + (tig << 1);
        float2 bz = *(const float2*)&bias[h * 64 + col];
        float2 r0, r1;
        r0.x = acc[n][0] * inv0 + bz.x;  r0.y = acc[n][1] * inv0 + bz.y;
        r1.x = acc[n][2] * inv1 + bz.x;  r1.y = acc[n][3] * inv1 + bz.y;
        *(float2*)&o0[col] = r0;
        *(float2*)&o1[col] = r1;
    }
}

// ---------------------------------------------------------------------------
extern "C" void kernel_launch(void* const* d_in, const int* in_sizes, int n_in,
                              void* d_out, int out_size) {
    (void)in_sizes; (void)n_in; (void)out_size;
    const float* x     = (const float*)d_in[0];
    const float* adj   = (const float*)d_in[1];
    const float* W     = (const float*)d_in[2];
    const float* a_src = (const float*)d_in[3];
    const float* a_dst = (const float*)d_in[4];
    const float* bias  = (const float*)d_in[5];
    float* out = (float*)d_out;

    cudaFuncSetAttribute(gemm_mma,
                         cudaFuncAttributeMaxDynamicSharedMemorySize, SMEM_GEMM);
    cudaFuncSetAttribute(attn_kernel,
                         cudaFuncAttributeMaxDynamicSharedMemorySize, SMEM_ATTN);

    wfrag_kernel<<<64, 256>>>(W);
    gemm_mma<<<128, 512, SMEM_GEMM>>>(x, a_src, a_dst);
    attn_kernel<<<dim3(8, 64), 256, SMEM_ATTN>>>(adj, bias, out);
}